// round 9
// baseline (speedup 1.0000x reference)
#include <cuda_runtime.h>
#include <math.h>

// ---------------------------------------------------------------------------
// Problem constants
// ---------------------------------------------------------------------------
#define LAYERS 4
#define NH     16
#define DM     1024
#define VO     32000
#define TT     2048
#define BBATCH 2
#define HDIM   64
#define BTOK   (BBATCH*TT)   // 4096

// ---------------------------------------------------------------------------
// Scratch (static __device__ arrays: the sanctioned no-alloc path)
// ---------------------------------------------------------------------------
__device__ float g_x   [(size_t)BTOK * DM];          // residual stream   16 MB
__device__ float g_h   [(size_t)BTOK * DM];          // layernorm output  16 MB
__device__ float g_qkv [(size_t)BTOK * 3 * DM];      // qkv               48 MB
__device__ float g_attn[(size_t)BTOK * DM];          // attn out          16 MB
__device__ float g_mid [(size_t)BTOK * 4 * DM];      // ffn mid           64 MB
__device__ float g_sc  [(size_t)BBATCH * NH * TT * TT]; // scores         536 MB

// ---------------------------------------------------------------------------
// Helpers
// ---------------------------------------------------------------------------
__device__ __forceinline__ float gelu_exact(float x) {
    return 0.5f * x * (1.0f + erff(x * 0.70710678118654752440f));
}

template <bool DOMAX>
__device__ __forceinline__ float block_reduce(float v) {
    __shared__ float sh[33];
    const int lane = threadIdx.x & 31;
    const int wid  = threadIdx.x >> 5;
#pragma unroll
    for (int o = 16; o; o >>= 1) {
        float t = __shfl_xor_sync(0xffffffffu, v, o);
        v = DOMAX ? fmaxf(v, t) : (v + t);
    }
    if (lane == 0) sh[wid] = v;
    __syncthreads();
    const int nw = blockDim.x >> 5;
    if (wid == 0) {
        float t = (lane < nw) ? sh[lane] : (DOMAX ? -3.4e38f : 0.0f);
#pragma unroll
        for (int o = 16; o; o >>= 1) {
            float u = __shfl_xor_sync(0xffffffffu, t, o);
            t = DOMAX ? fmaxf(t, u) : (t + u);
        }
        if (lane == 0) sh[32] = t;
    }
    __syncthreads();
    float r = sh[32];
    __syncthreads();   // safe reuse of sh on subsequent calls
    return r;
}

// ---------------------------------------------------------------------------
// Embedding: x[b,t,:] = tok_emb[id] + pos_emb[t] + context_emb[b]
// grid = BTOK blocks, 256 threads, float4 per thread
// ---------------------------------------------------------------------------
__global__ void embed_k(const int* __restrict__ ids,
                        const float* __restrict__ tok,
                        const float* __restrict__ pos,
                        const float* __restrict__ ctx,
                        float* __restrict__ x) {
    const int bt = blockIdx.x;
    const int b  = bt / TT;
    const int t  = bt - b * TT;
    const int id = ids[bt];
    const int d  = threadIdx.x * 4;
    const float4 a = *(const float4*)(tok + (size_t)id * DM + d);
    const float4 p = *(const float4*)(pos + (size_t)t  * DM + d);
    const float4 c = *(const float4*)(ctx + (size_t)b  * DM + d);
    float4 r;
    r.x = a.x + p.x + c.x; r.y = a.y + p.y + c.y;
    r.z = a.z + p.z + c.z; r.w = a.w + p.w + c.w;
    *(float4*)(x + (size_t)bt * DM + d) = r;
}

// ---------------------------------------------------------------------------
// LayerNorm over last dim D=1024. One block (256 threads) per row.
// ---------------------------------------------------------------------------
__global__ void layernorm_k(const float* __restrict__ xin,
                            float* __restrict__ yout,
                            const float* __restrict__ w,
                            const float* __restrict__ b) {
    const size_t row = blockIdx.x;
    const float* xr = xin + row * DM;
    float*       yr = yout + row * DM;
    const int d = threadIdx.x * 4;

    const float4 v = *(const float4*)(xr + d);
    float s  = v.x + v.y + v.z + v.w;
    float s2 = v.x*v.x + v.y*v.y + v.z*v.z + v.w*v.w;
    s  = block_reduce<false>(s);
    s2 = block_reduce<false>(s2);
    const float mean = s * (1.0f / DM);
    const float var  = s2 * (1.0f / DM) - mean * mean;
    const float rstd = rsqrtf(var + 1e-5f);

    const float4 ww = *(const float4*)(w + d);
    const float4 bb = *(const float4*)(b + d);
    float4 r;
    r.x = (v.x - mean) * rstd * ww.x + bb.x;
    r.y = (v.y - mean) * rstd * ww.y + bb.y;
    r.z = (v.z - mean) * rstd * ww.z + bb.z;
    r.w = (v.w - mean) * rstd * ww.w + bb.w;
    *(float4*)(yr + d) = r;
}

// ---------------------------------------------------------------------------
// Generic fp32 GEMM:  C[m,n] = epilogue( scale * sum_k A[m,k]*B(n,k) )
//   BTR=true : B(n,k) = B[n*ldb + k]   (NT: weight matrices [N,K] row-major)
//   BTR=false: B(n,k) = B[k*ldb + n]   (NN: P@V)
// Per-z (batch*head) pointer offsets: off = (z/nheads)*s?b + (z%nheads)*s?h
// causal_mode: 0 none; 1 skip tiles strictly above diagonal (scores);
//              2 clip K loop to m0+BM (P@V with zeroed upper triangle)
// Epilogue: *scale, +bias[n], optional exact GELU, optional residual add.
// All call sites use M%BM==0, N%BN==0, K%BK==0 (verified statically by shapes).
// ---------------------------------------------------------------------------
template <int BM, int BN, int BK, int TM, int TN, int NTH, bool BTR, bool DOGELU>
__global__ __launch_bounds__(NTH, 2)
void gemm_k(const float* __restrict__ A, long lda, long sAb, long sAh,
            const float* __restrict__ B, long ldb, long sBb, long sBh,
            float* __restrict__ C,       long ldc, long sCb, long sCh,
            int M, int N, int K, int nheads,
            const float* __restrict__ bias,
            const float* __restrict__ resid,
            float scale, int causal_mode) {
    const int z  = blockIdx.z;
    const int bb = z / nheads;
    const int hh = z - bb * nheads;
    A += (size_t)bb * sAb + (size_t)hh * sAh;
    B += (size_t)bb * sBb + (size_t)hh * sBh;
    const size_t coff = (size_t)bb * sCb + (size_t)hh * sCh;
    C += coff;
    if (resid) resid += coff;

    const int m0 = blockIdx.y * BM;
    const int n0 = blockIdx.x * BN;
    if (causal_mode == 1 && n0 > m0 + BM - 1) return;   // fully masked tile
    int Keff = K;
    if (causal_mode == 2) Keff = min(K, m0 + BM);       // P is 0 beyond row idx

    __shared__ float As[BK][BM + 4];
    __shared__ float Bs[BK][BN + 4];

    const int tid = threadIdx.x;
    const int tx  = tid % (BN / TN);
    const int ty  = tid / (BN / TN);

    float acc[TM][TN];
#pragma unroll
    for (int i = 0; i < TM; i++)
#pragma unroll
        for (int j = 0; j < TN; j++) acc[i][j] = 0.0f;

    for (int k0 = 0; k0 < Keff; k0 += BK) {
        // --- load A tile (BM x BK), transpose into As[BK][BM] ---
#pragma unroll
        for (int i = tid; i < BM * BK / 4; i += NTH) {
            const int r  = i / (BK / 4);
            const int c4 = i - r * (BK / 4);
            const float4 v = *(const float4*)(A + (size_t)(m0 + r) * lda + k0 + c4 * 4);
            As[c4 * 4 + 0][r] = v.x;
            As[c4 * 4 + 1][r] = v.y;
            As[c4 * 4 + 2][r] = v.z;
            As[c4 * 4 + 3][r] = v.w;
        }
        // --- load B tile into Bs[BK][BN] ---
        if (BTR) {
#pragma unroll
            for (int i = tid; i < BN * BK / 4; i += NTH) {
                const int r  = i / (BK / 4);
                const int c4 = i - r * (BK / 4);
                const float4 v = *(const float4*)(B + (size_t)(n0 + r) * ldb + k0 + c4 * 4);
                Bs[c4 * 4 + 0][r] = v.x;
                Bs[c4 * 4 + 1][r] = v.y;
                Bs[c4 * 4 + 2][r] = v.z;
                Bs[c4 * 4 + 3][r] = v.w;
            }
        } else {
#pragma unroll
            for (int i = tid; i < BK * BN / 4; i += NTH) {
                const int r  = i / (BN / 4);
                const int c4 = i - r * (BN / 4);
                const float4 v = *(const float4*)(B + (size_t)(k0 + r) * ldb + n0 + c4 * 4);
                *(float4*)&Bs[r][c4 * 4] = v;
            }
        }
        __syncthreads();

#pragma unroll
        for (int k = 0; k < BK; k++) {
            float a[TM], bf[TN];
#pragma unroll
            for (int i = 0; i < TM; i += 4)
                *(float4*)&a[i] = *(const float4*)&As[k][ty * TM + i];
#pragma unroll
            for (int j = 0; j < TN; j += 4)
                *(float4*)&bf[j] = *(const float4*)&Bs[k][tx * TN + j];
#pragma unroll
            for (int i = 0; i < TM; i++)
#pragma unroll
                for (int j = 0; j < TN; j++)
                    acc[i][j] = fmaf(a[i], bf[j], acc[i][j]);
        }
        __syncthreads();
    }

    // --- epilogue ---
#pragma unroll
    for (int i = 0; i < TM; i++) {
        const int m = m0 + ty * TM + i;
#pragma unroll
        for (int j = 0; j < TN; j++) {
            const int n = n0 + tx * TN + j;
            float v = acc[i][j] * scale;
            if (bias)  v += bias[n];
            if (DOGELU) v = gelu_exact(v);
            if (resid) v += resid[(size_t)m * ldc + n];
            C[(size_t)m * ldc + n] = v;
        }
    }
}

// ---------------------------------------------------------------------------
// Causal softmax in place over scores rows. grid=(T, B*H), 256 threads.
// Normalizes j in [0, i]; writes 0 for j in (i, T) so P@V can run dense tiles.
// ---------------------------------------------------------------------------
__global__ void softmax_k(float* __restrict__ S) {
    const int  i = blockIdx.x;
    const long z = blockIdx.y;
    float* row = S + (z * (long)TT + i) * (long)TT;
    const int len = i + 1;

    float m = -3.4e38f;
    for (int j = threadIdx.x; j < len; j += blockDim.x) m = fmaxf(m, row[j]);
    m = block_reduce<true>(m);

    float s = 0.0f;
    for (int j = threadIdx.x; j < len; j += blockDim.x) {
        const float e = __expf(row[j] - m);
        row[j] = e;
        s += e;
    }
    s = block_reduce<false>(s);
    const float inv = 1.0f / s;

    for (int j = threadIdx.x; j < len; j += blockDim.x) row[j] *= inv;
    for (int j = len + threadIdx.x; j < TT; j += blockDim.x) row[j] = 0.0f;
}

// ---------------------------------------------------------------------------
// Host orchestration
// ---------------------------------------------------------------------------
extern "C" void kernel_launch(void* const* d_in, const int* in_sizes, int n_in,
                              void* d_out, int out_size) {
    (void)in_sizes; (void)n_in; (void)out_size;
    const int*   ids   = (const int*)  d_in[0];
    const float* ctx   = (const float*)d_in[1];
    const float* tok   = (const float*)d_in[2];
    const float* pos   = (const float*)d_in[3];
    const float* qkvw  = (const float*)d_in[4];
    const float* qkvb  = (const float*)d_in[5];
    const float* projw = (const float*)d_in[6];
    const float* projb = (const float*)d_in[7];
    const float* ln1w  = (const float*)d_in[8];
    const float* ln1b  = (const float*)d_in[9];
    const float* ln2w  = (const float*)d_in[10];
    const float* ln2b  = (const float*)d_in[11];
    const float* f1w   = (const float*)d_in[12];
    const float* f1b   = (const float*)d_in[13];
    const float* f2w   = (const float*)d_in[14];
    const float* f2b   = (const float*)d_in[15];
    const float* lnfw  = (const float*)d_in[16];
    const float* lnfb  = (const float*)d_in[17];
    float* out = (float*)d_out;

    float *x, *h, *qkv, *attn, *mid, *sc;
    cudaGetSymbolAddress((void**)&x,    g_x);
    cudaGetSymbolAddress((void**)&h,    g_h);
    cudaGetSymbolAddress((void**)&qkv,  g_qkv);
    cudaGetSymbolAddress((void**)&attn, g_attn);
    cudaGetSymbolAddress((void**)&mid,  g_mid);
    cudaGetSymbolAddress((void**)&sc,   g_sc);

    const float attn_scale = 0.125f;  // 1/sqrt(64)

    embed_k<<<BTOK, 256>>>(ids, tok, pos, ctx, x);

    for (int l = 0; l < LAYERS; l++) {
        // ln1
        layernorm_k<<<BTOK, 256>>>(x, h, ln1w + (size_t)l * DM, ln1b + (size_t)l * DM);

        // qkv = h @ qkv_w^T + qkv_b      [4096, 3072]
        gemm_k<128,128,16,8,8,256,true,false><<<dim3(3*DM/128, BTOK/128, 1), 256>>>(
            h, DM, 0, 0,
            qkvw + (size_t)l * 3 * DM * DM, DM, 0, 0,
            qkv, 3*DM, 0, 0,
            BTOK, 3*DM, DM, 1,
            qkvb + (size_t)l * 3 * DM, nullptr, 1.0f, 0);

        // scores[z] = scale * Q @ K^T   (skip upper-triangle tiles)
        gemm_k<128,128,16,8,8,256,true,false><<<dim3(TT/128, TT/128, BBATCH*NH), 256>>>(
            qkv,        3*DM, (long)TT*3*DM, HDIM,
            qkv + DM,   3*DM, (long)TT*3*DM, HDIM,
            sc, TT, (long)NH*TT*TT, (long)TT*TT,
            TT, TT, HDIM, NH,
            nullptr, nullptr, attn_scale, 1);

        // causal softmax (zeros upper triangle)
        softmax_k<<<dim3(TT, BBATCH*NH), 256>>>(sc);

        // attn[z] = P @ V   (K loop clipped to m0+BM)
        gemm_k<128,64,16,8,4,256,false,false><<<dim3(1, TT/128, BBATCH*NH), 256>>>(
            sc, TT, (long)NH*TT*TT, (long)TT*TT,
            qkv + 2*DM, 3*DM, (long)TT*3*DM, HDIM,
            attn, DM, (long)TT*DM, HDIM,
            TT, HDIM, TT, NH,
            nullptr, nullptr, 1.0f, 2);

        // x += attn @ proj_w^T + proj_b
        gemm_k<128,128,16,8,8,256,true,false><<<dim3(DM/128, BTOK/128, 1), 256>>>(
            attn, DM, 0, 0,
            projw + (size_t)l * DM * DM, DM, 0, 0,
            x, DM, 0, 0,
            BTOK, DM, DM, 1,
            projb + (size_t)l * DM, x, 1.0f, 0);

        // ln2
        layernorm_k<<<BTOK, 256>>>(x, h, ln2w + (size_t)l * DM, ln2b + (size_t)l * DM);

        // mid = gelu(h @ f1_w^T + f1_b)   [4096, 4096]
        gemm_k<128,128,16,8,8,256,true,true><<<dim3(4*DM/128, BTOK/128, 1), 256>>>(
            h, DM, 0, 0,
            f1w + (size_t)l * 4 * DM * DM, DM, 0, 0,
            mid, 4*DM, 0, 0,
            BTOK, 4*DM, DM, 1,
            f1b + (size_t)l * 4 * DM, nullptr, 1.0f, 0);

        // x += mid @ f2_w^T + f2_b
        gemm_k<128,128,16,8,8,256,true,false><<<dim3(DM/128, BTOK/128, 1), 256>>>(
            mid, 4*DM, 0, 0,
            f2w + (size_t)l * DM * 4 * DM, 4*DM, 0, 0,
            x, DM, 0, 0,
            BTOK, DM, 4*DM, 1,
            f2b + (size_t)l * DM, x, 1.0f, 0);
    }

    // final layernorm
    layernorm_k<<<BTOK, 256>>>(x, h, lnfw, lnfb);

    // logits = h @ tok_emb^T   [4096, 32000]
    gemm_k<128,128,16,8,8,256,true,false><<<dim3(VO/128, BTOK/128, 1), 256>>>(
        h, DM, 0, 0,
        tok, DM, 0, 0,
        out, VO, 0, 0,
        BTOK, VO, DM, 1,
        nullptr, nullptr, 1.0f, 0);
}

// round 10
// speedup vs baseline: 1.9563x; 1.9563x over previous
#include <cuda_runtime.h>
#include <cuda_bf16.h>
#include <math.h>

// ---------------------------------------------------------------------------
// Problem constants
// ---------------------------------------------------------------------------
#define LAYERS 4
#define NH     16
#define DM     1024
#define VO     32000
#define TT     2048
#define BBATCH 2
#define HDIM   64
#define BTOK   (BBATCH*TT)   // 4096

// ---------------------------------------------------------------------------
// Scratch (static __device__ arrays: the sanctioned no-alloc path)
// ---------------------------------------------------------------------------
__device__ float g_x   [(size_t)BTOK * DM];
__device__ float g_h   [(size_t)BTOK * DM];
__device__ float g_qkv [(size_t)BTOK * 3 * DM];
__device__ float g_attn[(size_t)BTOK * DM];
__device__ float g_mid [(size_t)BTOK * 4 * DM];
__device__ float g_sc  [(size_t)BBATCH * NH * TT * TT];

// ---------------------------------------------------------------------------
// Helpers
// ---------------------------------------------------------------------------
__device__ __forceinline__ float gelu_exact(float x) {
    return 0.5f * x * (1.0f + erff(x * 0.70710678118654752440f));
}

template <bool DOMAX>
__device__ __forceinline__ float block_reduce(float v) {
    __shared__ float sh[33];
    const int lane = threadIdx.x & 31;
    const int wid  = threadIdx.x >> 5;
#pragma unroll
    for (int o = 16; o; o >>= 1) {
        float t = __shfl_xor_sync(0xffffffffu, v, o);
        v = DOMAX ? fmaxf(v, t) : (v + t);
    }
    if (lane == 0) sh[wid] = v;
    __syncthreads();
    const int nw = blockDim.x >> 5;
    if (wid == 0) {
        float t = (lane < nw) ? sh[lane] : (DOMAX ? -3.4e38f : 0.0f);
#pragma unroll
        for (int o = 16; o; o >>= 1) {
            float u = __shfl_xor_sync(0xffffffffu, t, o);
            t = DOMAX ? fmaxf(t, u) : (t + u);
        }
        if (lane == 0) sh[32] = t;
    }
    __syncthreads();
    float r = sh[32];
    __syncthreads();
    return r;
}

// split fp32 pair (x = even-k, y = odd-k) into hi/lo bf16x2 packed words
__device__ __forceinline__ void bf16_split_pack(float x, float y,
                                                unsigned& hi, unsigned& lo) {
    __nv_bfloat16 xh = __float2bfloat16(x);
    __nv_bfloat16 yh = __float2bfloat16(y);
    float xr = x - __bfloat162float(xh);
    float yr = y - __bfloat162float(yh);
    __nv_bfloat162 h2 = __halves2bfloat162(xh, yh);                      // .x = even k (low bits)
    __nv_bfloat162 l2 = __halves2bfloat162(__float2bfloat16(xr), __float2bfloat16(yr));
    hi = *reinterpret_cast<unsigned*>(&h2);
    lo = *reinterpret_cast<unsigned*>(&l2);
}

__device__ __forceinline__ void mma16816(float* c, const unsigned* a, const unsigned* b) {
    asm volatile(
        "mma.sync.aligned.m16n8k16.row.col.f32.bf16.bf16.f32 "
        "{%0,%1,%2,%3}, {%4,%5,%6,%7}, {%8,%9}, {%0,%1,%2,%3};\n"
        : "+f"(c[0]), "+f"(c[1]), "+f"(c[2]), "+f"(c[3])
        : "r"(a[0]), "r"(a[1]), "r"(a[2]), "r"(a[3]), "r"(b[0]), "r"(b[1]));
}

// ---------------------------------------------------------------------------
// Embedding
// ---------------------------------------------------------------------------
__global__ void embed_k(const int* __restrict__ ids,
                        const float* __restrict__ tok,
                        const float* __restrict__ pos,
                        const float* __restrict__ ctx,
                        float* __restrict__ x) {
    const int bt = blockIdx.x;
    const int b  = bt / TT;
    const int t  = bt - b * TT;
    const int id = ids[bt];
    const int d  = threadIdx.x * 4;
    const float4 a = *(const float4*)(tok + (size_t)id * DM + d);
    const float4 p = *(const float4*)(pos + (size_t)t  * DM + d);
    const float4 c = *(const float4*)(ctx + (size_t)b  * DM + d);
    float4 r;
    r.x = a.x + p.x + c.x; r.y = a.y + p.y + c.y;
    r.z = a.z + p.z + c.z; r.w = a.w + p.w + c.w;
    *(float4*)(x + (size_t)bt * DM + d) = r;
}

// ---------------------------------------------------------------------------
// LayerNorm
// ---------------------------------------------------------------------------
__global__ void layernorm_k(const float* __restrict__ xin,
                            float* __restrict__ yout,
                            const float* __restrict__ w,
                            const float* __restrict__ b) {
    const size_t row = blockIdx.x;
    const float* xr = xin + row * DM;
    float*       yr = yout + row * DM;
    const int d = threadIdx.x * 4;

    const float4 v = *(const float4*)(xr + d);
    float s  = v.x + v.y + v.z + v.w;
    float s2 = v.x*v.x + v.y*v.y + v.z*v.z + v.w*v.w;
    s  = block_reduce<false>(s);
    s2 = block_reduce<false>(s2);
    const float mean = s * (1.0f / DM);
    const float var  = s2 * (1.0f / DM) - mean * mean;
    const float rstd = rsqrtf(var + 1e-5f);

    const float4 ww = *(const float4*)(w + d);
    const float4 bb = *(const float4*)(b + d);
    float4 r;
    r.x = (v.x - mean) * rstd * ww.x + bb.x;
    r.y = (v.y - mean) * rstd * ww.y + bb.y;
    r.z = (v.z - mean) * rstd * ww.z + bb.z;
    r.w = (v.w - mean) * rstd * ww.w + bb.w;
    *(float4*)(yr + d) = r;
}

// ---------------------------------------------------------------------------
// Tensor-core GEMM, bf16x3 split emulation of fp32.
//   C[m,n] = epilogue( scale * sum_k A[m,k] * B(n,k) )
//   BTR=true : B(n,k) = B[n*ldb + k]   (weights [N,K] row-major)
//   BTR=false: B(n,k) = B[k*ldb + n]   (P@V)
// causal_mode: 0 none; 1 skip tiles strictly above diagonal; 2 clip K to m0+BM
// smem layout (per buffer), fragment-permuted so mainloop LDS is vectorized:
//   A: [kstep(BK/16)][mtile(BM/16)][plane(2)][lane(32)][word(4)]  (bf16x2 words)
//   B: [kstep       ][ntile(BN/8) ][plane(2)][lane(32)][word(2)]
// ---------------------------------------------------------------------------
template <int BM, int BN, int WM, int WN, bool BTR, bool DOGELU>
__global__ __launch_bounds__(256, 1)
void tgemm_k(const float* __restrict__ A, long lda, long sAb, long sAh,
             const float* __restrict__ B, long ldb, long sBb, long sBh,
             float* __restrict__ C,       long ldc, long sCb, long sCh,
             int M, int N, int K, int nheads,
             const float* __restrict__ bias,
             const float* __restrict__ resid,
             float scale, int causal_mode) {
    constexpr int BK     = 32;
    constexpr int KSTEPS = BK / 16;            // 2
    constexpr int NMT    = BM / 16;            // smem m-tiles
    constexpr int NNT    = BN / 8;             // smem n-tiles
    constexpr int AWORDS = KSTEPS * NMT * 2 * 32 * 4;
    constexpr int BWORDS = KSTEPS * NNT * 2 * 32 * 2;
    constexpr int MT     = BM / 16 / WM;       // m-tiles per warp
    constexpr int NT     = BN / 8  / WN;       // n-tiles per warp
    constexpr int ACHUNK = (BM * BK) / (4 * 256);
    constexpr int BCHUNK = (BN * BK) / (4 * 256);
    static_assert(BTR || (BN == 64), "NN path sized for BN=64");

    extern __shared__ unsigned smem_u[];
    unsigned* As = smem_u;                 // [2][AWORDS]
    unsigned* Bs = smem_u + 2 * AWORDS;    // [2][BWORDS]

    const int z  = blockIdx.z;
    const int bb = z / nheads;
    const int hh = z - bb * nheads;
    A += (size_t)bb * sAb + (size_t)hh * sAh;
    B += (size_t)bb * sBb + (size_t)hh * sBh;
    const size_t coff = (size_t)bb * sCb + (size_t)hh * sCh;
    C += coff;
    if (resid) resid += coff;

    const int m0 = blockIdx.y * BM;
    const int n0 = blockIdx.x * BN;
    if (causal_mode == 1 && n0 > m0 + BM - 1) return;
    int Keff = K;
    if (causal_mode == 2) Keff = min(K, m0 + BM);

    const int tid  = threadIdx.x;
    const int warp = tid >> 5;
    const int lane = tid & 31;
    const int wm   = warp % WM;
    const int wn   = warp / WM;

    float acc[MT][NT][4];
#pragma unroll
    for (int i = 0; i < MT; i++)
#pragma unroll
        for (int j = 0; j < NT; j++)
#pragma unroll
            for (int q = 0; q < 4; q++) acc[i][j][q] = 0.0f;

    float4 aR[ACHUNK];
    float4 bR[BTR ? BCHUNK : 2];

    // ---------------- staging helpers (inlined lambdas) ----------------
    auto ldgA = [&](int k0) {
#pragma unroll
        for (int c = 0; c < ACHUNK; c++) {
            const int idx = tid + c * 256;
            const int r   = idx >> 3;
            const int kc  = idx & 7;
            aR[c] = *(const float4*)(A + (size_t)(m0 + r) * lda + k0 + kc * 4);
        }
    };
    auto stsA = [&](int buf) {
        unsigned* dst = As + buf * AWORDS;
#pragma unroll
        for (int c = 0; c < ACHUNK; c++) {
            const int idx   = tid + c * 256;
            const int r     = idx >> 3;
            const int kc    = idx & 7;
            const int mtile = r >> 4;
            const int mloc  = r & 15;
            const int p0    = kc * 2;             // kpair of v.x/v.y
            const int kstep = p0 >> 3;
            const int kloc0 = p0 & 7;
            const int word  = ((kloc0 >= 4) ? 2 : 0) + ((mloc >= 8) ? 1 : 0);
            const int lane0 = ((mloc & 7) << 2) + (kloc0 & 3);
            unsigned* base = dst + (size_t)((kstep * NMT + mtile) * 2) * 128;
            unsigned h0, l0, h1, l1;
            bf16_split_pack(aR[c].x, aR[c].y, h0, l0);
            bf16_split_pack(aR[c].z, aR[c].w, h1, l1);
            base[lane0 * 4 + word]           = h0;
            base[(lane0 + 1) * 4 + word]     = h1;
            base[128 + lane0 * 4 + word]     = l0;
            base[128 + (lane0 + 1) * 4 + word] = l1;
        }
    };
    auto ldgB = [&](int k0) {
        if (BTR) {
#pragma unroll
            for (int c = 0; c < BCHUNK; c++) {
                const int idx = tid + c * 256;
                const int r   = idx >> 3;
                const int kc  = idx & 7;
                bR[c] = *(const float4*)(B + (size_t)(n0 + r) * ldb + k0 + kc * 4);
            }
        } else {
            const int p  = tid >> 4;              // kpair 0..15
            const int nq = tid & 15;
            bR[0] = *(const float4*)(B + (size_t)(k0 + 2 * p)     * ldb + n0 + nq * 4);
            bR[1] = *(const float4*)(B + (size_t)(k0 + 2 * p + 1) * ldb + n0 + nq * 4);
        }
    };
    auto stsB = [&](int buf) {
        unsigned* dst = Bs + buf * BWORDS;
        if (BTR) {
#pragma unroll
            for (int c = 0; c < BCHUNK; c++) {
                const int idx   = tid + c * 256;
                const int r     = idx >> 3;
                const int kc    = idx & 7;
                const int ntile = r >> 3;
                const int nloc  = r & 7;
                const int p0    = kc * 2;
                const int kstep = p0 >> 3;
                const int kloc0 = p0 & 7;
                const int word  = (kloc0 >= 4) ? 1 : 0;
                const int lane0 = (nloc << 2) + (kloc0 & 3);
                unsigned* base = dst + (size_t)((kstep * NNT + ntile) * 2) * 64;
                unsigned h0, l0, h1, l1;
                bf16_split_pack(bR[c].x, bR[c].y, h0, l0);
                bf16_split_pack(bR[c].z, bR[c].w, h1, l1);
                base[lane0 * 2 + word]            = h0;
                base[(lane0 + 1) * 2 + word]      = h1;
                base[64 + lane0 * 2 + word]       = l0;
                base[64 + (lane0 + 1) * 2 + word] = l1;
            }
        } else {
            const int p     = tid >> 4;
            const int nq    = tid & 15;
            const int kstep = p >> 3;
            const int kloc  = p & 7;
            const int word  = (kloc >= 4) ? 1 : 0;
            const float* v0 = (const float*)&bR[0];
            const float* v1 = (const float*)&bR[1];
#pragma unroll
            for (int j = 0; j < 4; j++) {
                const int n     = nq * 4 + j;
                const int ntile = n >> 3;
                const int nloc  = n & 7;
                const int lanej = (nloc << 2) + (kloc & 3);
                unsigned h, l;
                bf16_split_pack(v0[j], v1[j], h, l);
                unsigned* base = dst + (size_t)((kstep * NNT + ntile) * 2) * 64;
                base[lanej * 2 + word]      = h;
                base[64 + lanej * 2 + word] = l;
            }
        }
    };

    // ---------------- mainloop: double buffered ----------------
    const int nIt = Keff / BK;
    ldgA(0); ldgB(0);
    stsA(0); stsB(0);
    __syncthreads();

    for (int it = 0; it < nIt; it++) {
        const int cur = it & 1;
        const bool hasNext = (it + 1 < nIt);
        if (hasNext) { ldgA((it + 1) * BK); ldgB((it + 1) * BK); }

        const unsigned* uA = As + cur * AWORDS;
        const unsigned* uB = Bs + cur * BWORDS;
#pragma unroll
        for (int s = 0; s < KSTEPS; s++) {
            unsigned af[MT][2][4];
#pragma unroll
            for (int i = 0; i < MT; i++) {
                const int mt = wm * MT + i;
                const unsigned* pa = uA + (size_t)((s * NMT + mt) * 2) * 128 + (lane << 2);
                *(uint4*)af[i][0] = *(const uint4*)pa;
                *(uint4*)af[i][1] = *(const uint4*)(pa + 128);
            }
            unsigned bfr[NT][2][2];
#pragma unroll
            for (int j = 0; j < NT; j++) {
                const int nt = wn * NT + j;
                const unsigned* pb = uB + (size_t)((s * NNT + nt) * 2) * 64 + (lane << 1);
                *(uint2*)bfr[j][0] = *(const uint2*)pb;
                *(uint2*)bfr[j][1] = *(const uint2*)(pb + 64);
            }
#pragma unroll
            for (int i = 0; i < MT; i++)
#pragma unroll
                for (int j = 0; j < NT; j++) {
                    mma16816(acc[i][j], af[i][0], bfr[j][0]);   // hi*hi
                    mma16816(acc[i][j], af[i][0], bfr[j][1]);   // hi*lo
                    mma16816(acc[i][j], af[i][1], bfr[j][0]);   // lo*hi
                }
        }
        if (hasNext) { stsA(cur ^ 1); stsB(cur ^ 1); }
        __syncthreads();
    }

    // ---------------- epilogue ----------------
#pragma unroll
    for (int i = 0; i < MT; i++) {
        const int row = m0 + wm * (MT * 16) + i * 16 + (lane >> 2);
#pragma unroll
        for (int j = 0; j < NT; j++) {
            const int col = n0 + wn * (NT * 8) + j * 8 + ((lane & 3) << 1);
            float b0 = 0.f, b1 = 0.f;
            if (bias) { b0 = bias[col]; b1 = bias[col + 1]; }
#pragma unroll
            for (int half = 0; half < 2; half++) {
                const int r = row + half * 8;
                float v0 = acc[i][j][half * 2 + 0] * scale + b0;
                float v1 = acc[i][j][half * 2 + 1] * scale + b1;
                if (DOGELU) { v0 = gelu_exact(v0); v1 = gelu_exact(v1); }
                if (resid) {
                    const float2 rr = *(const float2*)(resid + (size_t)r * ldc + col);
                    v0 += rr.x; v1 += rr.y;
                }
                float2 o; o.x = v0; o.y = v1;
                *(float2*)(C + (size_t)r * ldc + col) = o;
            }
        }
    }
}

// ---------------------------------------------------------------------------
// Causal softmax in place (zeros upper triangle so P@V runs dense tiles)
// ---------------------------------------------------------------------------
__global__ void softmax_k(float* __restrict__ S) {
    const int  i = blockIdx.x;
    const long z = blockIdx.y;
    float* row = S + (z * (long)TT + i) * (long)TT;
    const int len = i + 1;

    float m = -3.4e38f;
    for (int j = threadIdx.x; j < len; j += blockDim.x) m = fmaxf(m, row[j]);
    m = block_reduce<true>(m);

    float s = 0.0f;
    for (int j = threadIdx.x; j < len; j += blockDim.x) {
        const float e = __expf(row[j] - m);
        row[j] = e;
        s += e;
    }
    s = block_reduce<false>(s);
    const float inv = 1.0f / s;

    for (int j = threadIdx.x; j < len; j += blockDim.x) row[j] *= inv;
    for (int j = len + threadIdx.x; j < TT; j += blockDim.x) row[j] = 0.0f;
}

// ---------------------------------------------------------------------------
// Host orchestration
// ---------------------------------------------------------------------------
using GemmNT  = void(*)(const float*, long, long, long, const float*, long, long, long,
                        float*, long, long, long, int, int, int, int,
                        const float*, const float*, float, int);

extern "C" void kernel_launch(void* const* d_in, const int* in_sizes, int n_in,
                              void* d_out, int out_size) {
    (void)in_sizes; (void)n_in; (void)out_size;
    const int*   ids   = (const int*)  d_in[0];
    const float* ctx   = (const float*)d_in[1];
    const float* tok   = (const float*)d_in[2];
    const float* pos   = (const float*)d_in[3];
    const float* qkvw  = (const float*)d_in[4];
    const float* qkvb  = (const float*)d_in[5];
    const float* projw = (const float*)d_in[6];
    const float* projb = (const float*)d_in[7];
    const float* ln1w  = (const float*)d_in[8];
    const float* ln1b  = (const float*)d_in[9];
    const float* ln2w  = (const float*)d_in[10];
    const float* ln2b  = (const float*)d_in[11];
    const float* f1w   = (const float*)d_in[12];
    const float* f1b   = (const float*)d_in[13];
    const float* f2w   = (const float*)d_in[14];
    const float* f2b   = (const float*)d_in[15];
    const float* lnfw  = (const float*)d_in[16];
    const float* lnfb  = (const float*)d_in[17];
    float* out = (float*)d_out;

    float *x, *h, *qkv, *attn, *mid, *sc;
    cudaGetSymbolAddress((void**)&x,    g_x);
    cudaGetSymbolAddress((void**)&h,    g_h);
    cudaGetSymbolAddress((void**)&qkv,  g_qkv);
    cudaGetSymbolAddress((void**)&attn, g_attn);
    cudaGetSymbolAddress((void**)&mid,  g_mid);
    cudaGetSymbolAddress((void**)&sc,   g_sc);

    // template instances
    auto kNT  = tgemm_k<128,128,2,4,true ,false>;   // generic NT
    auto kNTG = tgemm_k<128,128,2,4,true ,true >;   // NT + GELU
    auto kPV  = tgemm_k<128, 64,2,4,false,false>;   // P @ V (NN)

    const int SM_NT = 2 * (4096 + 4096) * 4;   // 64 KB
    const int SM_PV = 2 * (4096 + 2048) * 4;   // 48 KB
    cudaFuncSetAttribute(kNT,  cudaFuncAttributeMaxDynamicSharedMemorySize, SM_NT);
    cudaFuncSetAttribute(kNTG, cudaFuncAttributeMaxDynamicSharedMemorySize, SM_NT);
    cudaFuncSetAttribute(kPV,  cudaFuncAttributeMaxDynamicSharedMemorySize, SM_PV);

    const float attn_scale = 0.125f;  // 1/sqrt(64)

    embed_k<<<BTOK, 256>>>(ids, tok, pos, ctx, x);

    for (int l = 0; l < LAYERS; l++) {
        layernorm_k<<<BTOK, 256>>>(x, h, ln1w + (size_t)l * DM, ln1b + (size_t)l * DM);

        // qkv = h @ qkv_w^T + qkv_b
        kNT<<<dim3(3*DM/128, BTOK/128, 1), 256, SM_NT>>>(
            h, DM, 0, 0,
            qkvw + (size_t)l * 3 * DM * DM, DM, 0, 0,
            qkv, 3*DM, 0, 0,
            BTOK, 3*DM, DM, 1,
            qkvb + (size_t)l * 3 * DM, nullptr, 1.0f, 0);

        // scores = scale * Q @ K^T  (skip upper-triangle tiles)
        kNT<<<dim3(TT/128, TT/128, BBATCH*NH), 256, SM_NT>>>(
            qkv,      3*DM, (long)TT*3*DM, HDIM,
            qkv + DM, 3*DM, (long)TT*3*DM, HDIM,
            sc, TT, (long)NH*TT*TT, (long)TT*TT,
            TT, TT, HDIM, NH,
            nullptr, nullptr, attn_scale, 1);

        softmax_k<<<dim3(TT, BBATCH*NH), 256>>>(sc);

        // attn = P @ V   (K clipped to m0+128)
        kPV<<<dim3(1, TT/128, BBATCH*NH), 256, SM_PV>>>(
            sc, TT, (long)NH*TT*TT, (long)TT*TT,
            qkv + 2*DM, 3*DM, (long)TT*3*DM, HDIM,
            attn, DM, (long)TT*DM, HDIM,
            TT, HDIM, TT, NH,
            nullptr, nullptr, 1.0f, 2);

        // x += attn @ proj_w^T + proj_b
        kNT<<<dim3(DM/128, BTOK/128, 1), 256, SM_NT>>>(
            attn, DM, 0, 0,
            projw + (size_t)l * DM * DM, DM, 0, 0,
            x, DM, 0, 0,
            BTOK, DM, DM, 1,
            projb + (size_t)l * DM, x, 1.0f, 0);

        layernorm_k<<<BTOK, 256>>>(x, h, ln2w + (size_t)l * DM, ln2b + (size_t)l * DM);

        // mid = gelu(h @ f1_w^T + f1_b)
        kNTG<<<dim3(4*DM/128, BTOK/128, 1), 256, SM_NT>>>(
            h, DM, 0, 0,
            f1w + (size_t)l * 4 * DM * DM, DM, 0, 0,
            mid, 4*DM, 0, 0,
            BTOK, 4*DM, DM, 1,
            f1b + (size_t)l * 4 * DM, nullptr, 1.0f, 0);

        // x += mid @ f2_w^T + f2_b
        kNT<<<dim3(DM/128, BTOK/128, 1), 256, SM_NT>>>(
            mid, 4*DM, 0, 0,
            f2w + (size_t)l * DM * 4 * DM, 4*DM, 0, 0,
            x, DM, 0, 0,
            BTOK, DM, 4*DM, 1,
            f2b + (size_t)l * DM, x, 1.0f, 0);
    }

    layernorm_k<<<BTOK, 256>>>(x, h, lnfw, lnfb);

    // logits = h @ tok_emb^T
    kNT<<<dim3(VO/128, BTOK/128, 1), 256, SM_NT>>>(
        h, DM, 0, 0,
        tok, DM, 0, 0,
        out, VO, 0, 0,
        BTOK, VO, DM, 1,
        nullptr, nullptr, 1.0f, 0);
}

// round 11
// speedup vs baseline: 1.9574x; 1.0006x over previous
#include <cuda_runtime.h>
#include <cuda_bf16.h>
#include <math.h>

// ---------------------------------------------------------------------------
// Problem constants
// ---------------------------------------------------------------------------
#define LAYERS 4
#define NH     16
#define DM     1024
#define VO     32000
#define TT     2048
#define BBATCH 2
#define HDIM   64
#define BTOK   (BBATCH*TT)   // 4096

// ---------------------------------------------------------------------------
// Scratch (static __device__ arrays: the sanctioned no-alloc path)
// ---------------------------------------------------------------------------
__device__ float g_x   [(size_t)BTOK * DM];
__device__ float g_h   [(size_t)BTOK * DM];
__device__ float g_qkv [(size_t)BTOK * 3 * DM];
__device__ float g_attn[(size_t)BTOK * DM];
__device__ float g_mid [(size_t)BTOK * 4 * DM];
__device__ float g_sc  [(size_t)BBATCH * NH * TT * TT];

// ---------------------------------------------------------------------------
// Helpers
// ---------------------------------------------------------------------------
__device__ __forceinline__ float gelu_exact(float x) {
    return 0.5f * x * (1.0f + erff(x * 0.70710678118654752440f));
}

template <bool DOMAX>
__device__ __forceinline__ float block_reduce(float v) {
    __shared__ float sh[33];
    const int lane = threadIdx.x & 31;
    const int wid  = threadIdx.x >> 5;
#pragma unroll
    for (int o = 16; o; o >>= 1) {
        float t = __shfl_xor_sync(0xffffffffu, v, o);
        v = DOMAX ? fmaxf(v, t) : (v + t);
    }
    if (lane == 0) sh[wid] = v;
    __syncthreads();
    const int nw = blockDim.x >> 5;
    if (wid == 0) {
        float t = (lane < nw) ? sh[lane] : (DOMAX ? -3.4e38f : 0.0f);
#pragma unroll
        for (int o = 16; o; o >>= 1) {
            float u = __shfl_xor_sync(0xffffffffu, t, o);
            t = DOMAX ? fmaxf(t, u) : (t + u);
        }
        if (lane == 0) sh[32] = t;
    }
    __syncthreads();
    float r = sh[32];
    __syncthreads();
    return r;
}

// split fp32 pair (x = even-k, y = odd-k) into hi/lo bf16x2 packed words
__device__ __forceinline__ void bf16_split_pack(float x, float y,
                                                unsigned& hi, unsigned& lo) {
    __nv_bfloat16 xh = __float2bfloat16(x);
    __nv_bfloat16 yh = __float2bfloat16(y);
    float xr = x - __bfloat162float(xh);
    float yr = y - __bfloat162float(yh);
    __nv_bfloat162 h2 = __halves2bfloat162(xh, yh);                      // .x = even k (low bits)
    __nv_bfloat162 l2 = __halves2bfloat162(__float2bfloat16(xr), __float2bfloat16(yr));
    hi = *reinterpret_cast<unsigned*>(&h2);
    lo = *reinterpret_cast<unsigned*>(&l2);
}

__device__ __forceinline__ void mma16816(float* c, const unsigned* a, const unsigned* b) {
    asm volatile(
        "mma.sync.aligned.m16n8k16.row.col.f32.bf16.bf16.f32 "
        "{%0,%1,%2,%3}, {%4,%5,%6,%7}, {%8,%9}, {%0,%1,%2,%3};\n"
        : "+f"(c[0]), "+f"(c[1]), "+f"(c[2]), "+f"(c[3])
        : "r"(a[0]), "r"(a[1]), "r"(a[2]), "r"(a[3]), "r"(b[0]), "r"(b[1]));
}

// ---------------------------------------------------------------------------
// Embedding
// ---------------------------------------------------------------------------
__global__ void embed_k(const int* __restrict__ ids,
                        const float* __restrict__ tok,
                        const float* __restrict__ pos,
                        const float* __restrict__ ctx,
                        float* __restrict__ x) {
    const int bt = blockIdx.x;
    const int b  = bt / TT;
    const int t  = bt - b * TT;
    const int id = ids[bt];
    const int d  = threadIdx.x * 4;
    const float4 a = *(const float4*)(tok + (size_t)id * DM + d);
    const float4 p = *(const float4*)(pos + (size_t)t  * DM + d);
    const float4 c = *(const float4*)(ctx + (size_t)b  * DM + d);
    float4 r;
    r.x = a.x + p.x + c.x; r.y = a.y + p.y + c.y;
    r.z = a.z + p.z + c.z; r.w = a.w + p.w + c.w;
    *(float4*)(x + (size_t)bt * DM + d) = r;
}

// ---------------------------------------------------------------------------
// LayerNorm
// ---------------------------------------------------------------------------
__global__ void layernorm_k(const float* __restrict__ xin,
                            float* __restrict__ yout,
                            const float* __restrict__ w,
                            const float* __restrict__ b) {
    const size_t row = blockIdx.x;
    const float* xr = xin + row * DM;
    float*       yr = yout + row * DM;
    const int d = threadIdx.x * 4;

    const float4 v = *(const float4*)(xr + d);
    float s  = v.x + v.y + v.z + v.w;
    float s2 = v.x*v.x + v.y*v.y + v.z*v.z + v.w*v.w;
    s  = block_reduce<false>(s);
    s2 = block_reduce<false>(s2);
    const float mean = s * (1.0f / DM);
    const float var  = s2 * (1.0f / DM) - mean * mean;
    const float rstd = rsqrtf(var + 1e-5f);

    const float4 ww = *(const float4*)(w + d);
    const float4 bb = *(const float4*)(b + d);
    float4 r;
    r.x = (v.x - mean) * rstd * ww.x + bb.x;
    r.y = (v.y - mean) * rstd * ww.y + bb.y;
    r.z = (v.z - mean) * rstd * ww.z + bb.z;
    r.w = (v.w - mean) * rstd * ww.w + bb.w;
    *(float4*)(yr + d) = r;
}

// ---------------------------------------------------------------------------
// Tensor-core GEMM, bf16x3 split emulation of fp32.
//   C[m,n] = epilogue( scale * sum_k A[m,k] * B(n,k) )
//   BTR=true : B(n,k) = B[n*ldb + k]   (weights [N,K] row-major)
//   BTR=false: B(n,k) = B[k*ldb + n]   (P@V)
// causal_mode: 0 none; 1 skip tiles strictly above diagonal; 2 clip K to m0+BM
// smem layout (per buffer), fragment-permuted so mainloop LDS is vectorized:
//   A: [kstep(BK/16)][mtile(BM/16)][plane(2)][lane(32)][word(4)]  (bf16x2 words)
//   B: [kstep       ][ntile(BN/8) ][plane(2)][lane(32)][word(2)]
// ---------------------------------------------------------------------------
template <int BM, int BN, int WM, int WN, bool BTR, bool DOGELU>
__global__ __launch_bounds__(256, 1)
void tgemm_k(const float* __restrict__ A, long lda, long sAb, long sAh,
             const float* __restrict__ B, long ldb, long sBb, long sBh,
             float* __restrict__ C,       long ldc, long sCb, long sCh,
             int M, int N, int K, int nheads,
             const float* __restrict__ bias,
             const float* __restrict__ resid,
             float scale, int causal_mode) {
    constexpr int BK     = 32;
    constexpr int KSTEPS = BK / 16;            // 2
    constexpr int NMT    = BM / 16;            // smem m-tiles
    constexpr int NNT    = BN / 8;             // smem n-tiles
    constexpr int AWORDS = KSTEPS * NMT * 2 * 32 * 4;
    constexpr int BWORDS = KSTEPS * NNT * 2 * 32 * 2;
    constexpr int MT     = BM / 16 / WM;       // m-tiles per warp
    constexpr int NT     = BN / 8  / WN;       // n-tiles per warp
    constexpr int ACHUNK = (BM * BK) / (4 * 256);
    constexpr int BCHUNK = (BN * BK) / (4 * 256);
    static_assert(BTR || (BN == 64), "NN path sized for BN=64");

    extern __shared__ unsigned smem_u[];
    unsigned* As = smem_u;                 // [2][AWORDS]
    unsigned* Bs = smem_u + 2 * AWORDS;    // [2][BWORDS]

    const int z  = blockIdx.z;
    const int bb = z / nheads;
    const int hh = z - bb * nheads;
    A += (size_t)bb * sAb + (size_t)hh * sAh;
    B += (size_t)bb * sBb + (size_t)hh * sBh;
    const size_t coff = (size_t)bb * sCb + (size_t)hh * sCh;
    C += coff;
    if (resid) resid += coff;

    const int m0 = blockIdx.y * BM;
    const int n0 = blockIdx.x * BN;
    if (causal_mode == 1 && n0 > m0 + BM - 1) return;
    int Keff = K;
    if (causal_mode == 2) Keff = min(K, m0 + BM);

    const int tid  = threadIdx.x;
    const int warp = tid >> 5;
    const int lane = tid & 31;
    const int wm   = warp % WM;
    const int wn   = warp / WM;

    float acc[MT][NT][4];
#pragma unroll
    for (int i = 0; i < MT; i++)
#pragma unroll
        for (int j = 0; j < NT; j++)
#pragma unroll
            for (int q = 0; q < 4; q++) acc[i][j][q] = 0.0f;

    float4 aR[ACHUNK];
    float4 bR[BTR ? BCHUNK : 2];

    // ---------------- staging helpers (inlined lambdas) ----------------
    auto ldgA = [&](int k0) {
#pragma unroll
        for (int c = 0; c < ACHUNK; c++) {
            const int idx = tid + c * 256;
            const int r   = idx >> 3;
            const int kc  = idx & 7;
            aR[c] = *(const float4*)(A + (size_t)(m0 + r) * lda + k0 + kc * 4);
        }
    };
    auto stsA = [&](int buf) {
        unsigned* dst = As + buf * AWORDS;
#pragma unroll
        for (int c = 0; c < ACHUNK; c++) {
            const int idx   = tid + c * 256;
            const int r     = idx >> 3;
            const int kc    = idx & 7;
            const int mtile = r >> 4;
            const int mloc  = r & 15;
            const int p0    = kc * 2;             // kpair of v.x/v.y
            const int kstep = p0 >> 3;
            const int kloc0 = p0 & 7;
            const int word  = ((kloc0 >= 4) ? 2 : 0) + ((mloc >= 8) ? 1 : 0);
            const int lane0 = ((mloc & 7) << 2) + (kloc0 & 3);
            unsigned* base = dst + (size_t)((kstep * NMT + mtile) * 2) * 128;
            unsigned h0, l0, h1, l1;
            bf16_split_pack(aR[c].x, aR[c].y, h0, l0);
            bf16_split_pack(aR[c].z, aR[c].w, h1, l1);
            base[lane0 * 4 + word]           = h0;
            base[(lane0 + 1) * 4 + word]     = h1;
            base[128 + lane0 * 4 + word]     = l0;
            base[128 + (lane0 + 1) * 4 + word] = l1;
        }
    };
    auto ldgB = [&](int k0) {
        if (BTR) {
#pragma unroll
            for (int c = 0; c < BCHUNK; c++) {
                const int idx = tid + c * 256;
                const int r   = idx >> 3;
                const int kc  = idx & 7;
                bR[c] = *(const float4*)(B + (size_t)(n0 + r) * ldb + k0 + kc * 4);
            }
        } else {
            const int p  = tid >> 4;              // kpair 0..15
            const int nq = tid & 15;
            bR[0] = *(const float4*)(B + (size_t)(k0 + 2 * p)     * ldb + n0 + nq * 4);
            bR[1] = *(const float4*)(B + (size_t)(k0 + 2 * p + 1) * ldb + n0 + nq * 4);
        }
    };
    auto stsB = [&](int buf) {
        unsigned* dst = Bs + buf * BWORDS;
        if (BTR) {
#pragma unroll
            for (int c = 0; c < BCHUNK; c++) {
                const int idx   = tid + c * 256;
                const int r     = idx >> 3;
                const int kc    = idx & 7;
                const int ntile = r >> 3;
                const int nloc  = r & 7;
                const int p0    = kc * 2;
                const int kstep = p0 >> 3;
                const int kloc0 = p0 & 7;
                const int word  = (kloc0 >= 4) ? 1 : 0;
                const int lane0 = (nloc << 2) + (kloc0 & 3);
                unsigned* base = dst + (size_t)((kstep * NNT + ntile) * 2) * 64;
                unsigned h0, l0, h1, l1;
                bf16_split_pack(bR[c].x, bR[c].y, h0, l0);
                bf16_split_pack(bR[c].z, bR[c].w, h1, l1);
                base[lane0 * 2 + word]            = h0;
                base[(lane0 + 1) * 2 + word]      = h1;
                base[64 + lane0 * 2 + word]       = l0;
                base[64 + (lane0 + 1) * 2 + word] = l1;
            }
        } else {
            const int p     = tid >> 4;
            const int nq    = tid & 15;
            const int kstep = p >> 3;
            const int kloc  = p & 7;
            const int word  = (kloc >= 4) ? 1 : 0;
            const float* v0 = (const float*)&bR[0];
            const float* v1 = (const float*)&bR[1];
#pragma unroll
            for (int j = 0; j < 4; j++) {
                const int n     = nq * 4 + j;
                const int ntile = n >> 3;
                const int nloc  = n & 7;
                const int lanej = (nloc << 2) + (kloc & 3);
                unsigned h, l;
                bf16_split_pack(v0[j], v1[j], h, l);
                unsigned* base = dst + (size_t)((kstep * NNT + ntile) * 2) * 64;
                base[lanej * 2 + word]      = h;
                base[64 + lanej * 2 + word] = l;
            }
        }
    };

    // ---------------- mainloop: double buffered ----------------
    const int nIt = Keff / BK;
    ldgA(0); ldgB(0);
    stsA(0); stsB(0);
    __syncthreads();

    for (int it = 0; it < nIt; it++) {
        const int cur = it & 1;
        const bool hasNext = (it + 1 < nIt);
        if (hasNext) { ldgA((it + 1) * BK); ldgB((it + 1) * BK); }

        const unsigned* uA = As + cur * AWORDS;
        const unsigned* uB = Bs + cur * BWORDS;
#pragma unroll
        for (int s = 0; s < KSTEPS; s++) {
            unsigned af[MT][2][4];
#pragma unroll
            for (int i = 0; i < MT; i++) {
                const int mt = wm * MT + i;
                const unsigned* pa = uA + (size_t)((s * NMT + mt) * 2) * 128 + (lane << 2);
                *(uint4*)af[i][0] = *(const uint4*)pa;
                *(uint4*)af[i][1] = *(const uint4*)(pa + 128);
            }
            unsigned bfr[NT][2][2];
#pragma unroll
            for (int j = 0; j < NT; j++) {
                const int nt = wn * NT + j;
                const unsigned* pb = uB + (size_t)((s * NNT + nt) * 2) * 64 + (lane << 1);
                *(uint2*)bfr[j][0] = *(const uint2*)pb;
                *(uint2*)bfr[j][1] = *(const uint2*)(pb + 64);
            }
#pragma unroll
            for (int i = 0; i < MT; i++)
#pragma unroll
                for (int j = 0; j < NT; j++) {
                    mma16816(acc[i][j], af[i][0], bfr[j][0]);   // hi*hi
                    mma16816(acc[i][j], af[i][0], bfr[j][1]);   // hi*lo
                    mma16816(acc[i][j], af[i][1], bfr[j][0]);   // lo*hi
                }
        }
        if (hasNext) { stsA(cur ^ 1); stsB(cur ^ 1); }
        __syncthreads();
    }

    // ---------------- epilogue ----------------
#pragma unroll
    for (int i = 0; i < MT; i++) {
        const int row = m0 + wm * (MT * 16) + i * 16 + (lane >> 2);
#pragma unroll
        for (int j = 0; j < NT; j++) {
            const int col = n0 + wn * (NT * 8) + j * 8 + ((lane & 3) << 1);
            float b0 = 0.f, b1 = 0.f;
            if (bias) { b0 = bias[col]; b1 = bias[col + 1]; }
#pragma unroll
            for (int half = 0; half < 2; half++) {
                const int r = row + half * 8;
                float v0 = acc[i][j][half * 2 + 0] * scale + b0;
                float v1 = acc[i][j][half * 2 + 1] * scale + b1;
                if (DOGELU) { v0 = gelu_exact(v0); v1 = gelu_exact(v1); }
                if (resid) {
                    const float2 rr = *(const float2*)(resid + (size_t)r * ldc + col);
                    v0 += rr.x; v1 += rr.y;
                }
                float2 o; o.x = v0; o.y = v1;
                *(float2*)(C + (size_t)r * ldc + col) = o;
            }
        }
    }
}

// ---------------------------------------------------------------------------
// Causal softmax in place (zeros upper triangle so P@V runs dense tiles)
// ---------------------------------------------------------------------------
__global__ void softmax_k(float* __restrict__ S) {
    const int  i = blockIdx.x;
    const long z = blockIdx.y;
    float* row = S + (z * (long)TT + i) * (long)TT;
    const int len = i + 1;

    float m = -3.4e38f;
    for (int j = threadIdx.x; j < len; j += blockDim.x) m = fmaxf(m, row[j]);
    m = block_reduce<true>(m);

    float s = 0.0f;
    for (int j = threadIdx.x; j < len; j += blockDim.x) {
        const float e = __expf(row[j] - m);
        row[j] = e;
        s += e;
    }
    s = block_reduce<false>(s);
    const float inv = 1.0f / s;

    for (int j = threadIdx.x; j < len; j += blockDim.x) row[j] *= inv;
    for (int j = len + threadIdx.x; j < TT; j += blockDim.x) row[j] = 0.0f;
}

// ---------------------------------------------------------------------------
// Host orchestration
// ---------------------------------------------------------------------------
using GemmNT  = void(*)(const float*, long, long, long, const float*, long, long, long,
                        float*, long, long, long, int, int, int, int,
                        const float*, const float*, float, int);

extern "C" void kernel_launch(void* const* d_in, const int* in_sizes, int n_in,
                              void* d_out, int out_size) {
    (void)in_sizes; (void)n_in; (void)out_size;
    const int*   ids   = (const int*)  d_in[0];
    const float* ctx   = (const float*)d_in[1];
    const float* tok   = (const float*)d_in[2];
    const float* pos   = (const float*)d_in[3];
    const float* qkvw  = (const float*)d_in[4];
    const float* qkvb  = (const float*)d_in[5];
    const float* projw = (const float*)d_in[6];
    const float* projb = (const float*)d_in[7];
    const float* ln1w  = (const float*)d_in[8];
    const float* ln1b  = (const float*)d_in[9];
    const float* ln2w  = (const float*)d_in[10];
    const float* ln2b  = (const float*)d_in[11];
    const float* f1w   = (const float*)d_in[12];
    const float* f1b   = (const float*)d_in[13];
    const float* f2w   = (const float*)d_in[14];
    const float* f2b   = (const float*)d_in[15];
    const float* lnfw  = (const float*)d_in[16];
    const float* lnfb  = (const float*)d_in[17];
    float* out = (float*)d_out;

    float *x, *h, *qkv, *attn, *mid, *sc;
    cudaGetSymbolAddress((void**)&x,    g_x);
    cudaGetSymbolAddress((void**)&h,    g_h);
    cudaGetSymbolAddress((void**)&qkv,  g_qkv);
    cudaGetSymbolAddress((void**)&attn, g_attn);
    cudaGetSymbolAddress((void**)&mid,  g_mid);
    cudaGetSymbolAddress((void**)&sc,   g_sc);

    // template instances
    auto kNT  = tgemm_k<128,128,2,4,true ,false>;   // generic NT
    auto kNTG = tgemm_k<128,128,2,4,true ,true >;   // NT + GELU
    auto kPV  = tgemm_k<128, 64,2,4,false,false>;   // P @ V (NN)

    const int SM_NT = 2 * (4096 + 4096) * 4;   // 64 KB
    const int SM_PV = 2 * (4096 + 2048) * 4;   // 48 KB
    cudaFuncSetAttribute(kNT,  cudaFuncAttributeMaxDynamicSharedMemorySize, SM_NT);
    cudaFuncSetAttribute(kNTG, cudaFuncAttributeMaxDynamicSharedMemorySize, SM_NT);
    cudaFuncSetAttribute(kPV,  cudaFuncAttributeMaxDynamicSharedMemorySize, SM_PV);

    const float attn_scale = 0.125f;  // 1/sqrt(64)

    embed_k<<<BTOK, 256>>>(ids, tok, pos, ctx, x);

    for (int l = 0; l < LAYERS; l++) {
        layernorm_k<<<BTOK, 256>>>(x, h, ln1w + (size_t)l * DM, ln1b + (size_t)l * DM);

        // qkv = h @ qkv_w^T + qkv_b
        kNT<<<dim3(3*DM/128, BTOK/128, 1), 256, SM_NT>>>(
            h, DM, 0, 0,
            qkvw + (size_t)l * 3 * DM * DM, DM, 0, 0,
            qkv, 3*DM, 0, 0,
            BTOK, 3*DM, DM, 1,
            qkvb + (size_t)l * 3 * DM, nullptr, 1.0f, 0);

        // scores = scale * Q @ K^T  (skip upper-triangle tiles)
        kNT<<<dim3(TT/128, TT/128, BBATCH*NH), 256, SM_NT>>>(
            qkv,      3*DM, (long)TT*3*DM, HDIM,
            qkv + DM, 3*DM, (long)TT*3*DM, HDIM,
            sc, TT, (long)NH*TT*TT, (long)TT*TT,
            TT, TT, HDIM, NH,
            nullptr, nullptr, attn_scale, 1);

        softmax_k<<<dim3(TT, BBATCH*NH), 256>>>(sc);

        // attn = P @ V   (K clipped to m0+128)
        kPV<<<dim3(1, TT/128, BBATCH*NH), 256, SM_PV>>>(
            sc, TT, (long)NH*TT*TT, (long)TT*TT,
            qkv + 2*DM, 3*DM, (long)TT*3*DM, HDIM,
            attn, DM, (long)TT*DM, HDIM,
            TT, HDIM, TT, NH,
            nullptr, nullptr, 1.0f, 2);

        // x += attn @ proj_w^T + proj_b
        kNT<<<dim3(DM/128, BTOK/128, 1), 256, SM_NT>>>(
            attn, DM, 0, 0,
            projw + (size_t)l * DM * DM, DM, 0, 0,
            x, DM, 0, 0,
            BTOK, DM, DM, 1,
            projb + (size_t)l * DM, x, 1.0f, 0);

        layernorm_k<<<BTOK, 256>>>(x, h, ln2w + (size_t)l * DM, ln2b + (size_t)l * DM);

        // mid = gelu(h @ f1_w^T + f1_b)
        kNTG<<<dim3(4*DM/128, BTOK/128, 1), 256, SM_NT>>>(
            h, DM, 0, 0,
            f1w + (size_t)l * 4 * DM * DM, DM, 0, 0,
            mid, 4*DM, 0, 0,
            BTOK, 4*DM, DM, 1,
            f1b + (size_t)l * 4 * DM, nullptr, 1.0f, 0);

        // x += mid @ f2_w^T + f2_b
        kNT<<<dim3(DM/128, BTOK/128, 1), 256, SM_NT>>>(
            mid, 4*DM, 0, 0,
            f2w + (size_t)l * DM * 4 * DM, 4*DM, 0, 0,
            x, DM, 0, 0,
            BTOK, DM, 4*DM, 1,
            f2b + (size_t)l * DM, x, 1.0f, 0);
    }

    layernorm_k<<<BTOK, 256>>>(x, h, lnfw, lnfb);

    // logits = h @ tok_emb^T
    kNT<<<dim3(VO/128, BTOK/128, 1), 256, SM_NT>>>(
        h, DM, 0, 0,
        tok, DM, 0, 0,
        out, VO, 0, 0,
        BTOK, VO, DM, 1,
        nullptr, nullptr, 1.0f, 0);
}

// round 12
// speedup vs baseline: 2.1159x; 1.0810x over previous
#include <cuda_runtime.h>
#include <cuda_bf16.h>
#include <math.h>

// ---------------------------------------------------------------------------
// Problem constants
// ---------------------------------------------------------------------------
#define LAYERS 4
#define NH     16
#define DM     1024
#define VO     32000
#define TT     2048
#define BBATCH 2
#define HDIM   64
#define BTOK   (BBATCH*TT)   // 4096

// weight-plane offsets (elements)
#define QW_SZ  ((size_t)LAYERS*3*DM*DM)      // 12,582,912
#define PW_SZ  ((size_t)LAYERS*DM*DM)        //  4,194,304
#define F1_SZ  ((size_t)LAYERS*4*DM*DM)      // 16,777,216
#define F2_SZ  ((size_t)LAYERS*4*DM*DM)      // 16,777,216
#define TK_SZ  ((size_t)VO*DM)               // 32,768,000
#define QW_OFF ((size_t)0)
#define PW_OFF (QW_OFF+QW_SZ)
#define F1_OFF (PW_OFF+PW_SZ)
#define F2_OFF (F1_OFF+F1_SZ)
#define TK_OFF (F2_OFF+F2_SZ)
#define W_TOTAL (TK_OFF+TK_SZ)

// ---------------------------------------------------------------------------
// Scratch (static __device__ arrays: the sanctioned no-alloc path)
// ---------------------------------------------------------------------------
__device__ float g_x [(size_t)BTOK * DM];                 // residual (fp32)
__device__ float g_sc[(size_t)BBATCH * NH * TT * TT];     // scores   (fp32)

__device__ __nv_bfloat16 g_h_hi  [(size_t)BTOK * DM];
__device__ __nv_bfloat16 g_h_lo  [(size_t)BTOK * DM];
__device__ __nv_bfloat16 g_qkv_hi[(size_t)BTOK * 3 * DM];
__device__ __nv_bfloat16 g_qkv_lo[(size_t)BTOK * 3 * DM];
__device__ __nv_bfloat16 g_at_hi [(size_t)BTOK * DM];
__device__ __nv_bfloat16 g_at_lo [(size_t)BTOK * DM];
__device__ __nv_bfloat16 g_mid_hi[(size_t)BTOK * 4 * DM];
__device__ __nv_bfloat16 g_mid_lo[(size_t)BTOK * 4 * DM];
__device__ __nv_bfloat16 g_p_hi  [(size_t)BBATCH * NH * TT * TT];
__device__ __nv_bfloat16 g_p_lo  [(size_t)BBATCH * NH * TT * TT];
__device__ __nv_bfloat16 g_w_hi  [W_TOTAL];
__device__ __nv_bfloat16 g_w_lo  [W_TOTAL];

// ---------------------------------------------------------------------------
// Small helpers
// ---------------------------------------------------------------------------
__device__ __forceinline__ float gelu_exact(float x) {
    return 0.5f * x * (1.0f + erff(x * 0.70710678118654752440f));
}
__device__ __forceinline__ void split1(float v, __nv_bfloat16& h, __nv_bfloat16& l) {
    h = __float2bfloat16(v);
    l = __float2bfloat16(v - __bfloat162float(h));
}

template <bool DOMAX>
__device__ __forceinline__ float block_reduce(float v) {
    __shared__ float sh[33];
    const int lane = threadIdx.x & 31;
    const int wid  = threadIdx.x >> 5;
#pragma unroll
    for (int o = 16; o; o >>= 1) {
        float t = __shfl_xor_sync(0xffffffffu, v, o);
        v = DOMAX ? fmaxf(v, t) : (v + t);
    }
    if (lane == 0) sh[wid] = v;
    __syncthreads();
    const int nw = blockDim.x >> 5;
    if (wid == 0) {
        float t = (lane < nw) ? sh[lane] : (DOMAX ? -3.4e38f : 0.0f);
#pragma unroll
        for (int o = 16; o; o >>= 1) {
            float u = __shfl_xor_sync(0xffffffffu, t, o);
            t = DOMAX ? fmaxf(t, u) : (t + u);
        }
        if (lane == 0) sh[32] = t;
    }
    __syncthreads();
    float r = sh[32];
    __syncthreads();
    return r;
}

__device__ __forceinline__ void mma16816(float* c, const unsigned* a, const unsigned* b) {
    asm volatile(
        "mma.sync.aligned.m16n8k16.row.col.f32.bf16.bf16.f32 "
        "{%0,%1,%2,%3}, {%4,%5,%6,%7}, {%8,%9}, {%0,%1,%2,%3};\n"
        : "+f"(c[0]), "+f"(c[1]), "+f"(c[2]), "+f"(c[3])
        : "r"(a[0]), "r"(a[1]), "r"(a[2]), "r"(a[3]), "r"(b[0]), "r"(b[1]));
}
__device__ __forceinline__ void ldsm4(unsigned* r, unsigned a) {
    asm volatile("ldmatrix.sync.aligned.m8n8.x4.shared.b16 {%0,%1,%2,%3}, [%4];"
                 : "=r"(r[0]), "=r"(r[1]), "=r"(r[2]), "=r"(r[3]) : "r"(a));
}
__device__ __forceinline__ void ldsm4t(unsigned* r, unsigned a) {
    asm volatile("ldmatrix.sync.aligned.m8n8.x4.trans.shared.b16 {%0,%1,%2,%3}, [%4];"
                 : "=r"(r[0]), "=r"(r[1]), "=r"(r[2]), "=r"(r[3]) : "r"(a));
}
__device__ __forceinline__ void cp16(unsigned saddr, const void* g) {
    asm volatile("cp.async.cg.shared.global [%0], [%1], 16;" :: "r"(saddr), "l"(g));
}
__device__ __forceinline__ void cp_commit() { asm volatile("cp.async.commit_group;"); }
template <int N>
__device__ __forceinline__ void cp_wait() { asm volatile("cp.async.wait_group %0;" :: "n"(N)); }

// ---------------------------------------------------------------------------
// fp32 -> bf16 hi/lo split (weights)
// ---------------------------------------------------------------------------
__global__ void split_k(const float* __restrict__ s,
                        __nv_bfloat16* __restrict__ hi,
                        __nv_bfloat16* __restrict__ lo, long n4) {
    long i = (long)blockIdx.x * blockDim.x + threadIdx.x;
    const long stride = (long)gridDim.x * blockDim.x;
    for (; i < n4; i += stride) {
        float4 v = ((const float4*)s)[i];
        __nv_bfloat16 h0,h1,h2,h3,l0,l1,l2,l3;
        split1(v.x,h0,l0); split1(v.y,h1,l1); split1(v.z,h2,l2); split1(v.w,h3,l3);
        ((__nv_bfloat162*)hi)[2*i+0] = __halves2bfloat162(h0,h1);
        ((__nv_bfloat162*)hi)[2*i+1] = __halves2bfloat162(h2,h3);
        ((__nv_bfloat162*)lo)[2*i+0] = __halves2bfloat162(l0,l1);
        ((__nv_bfloat162*)lo)[2*i+1] = __halves2bfloat162(l2,l3);
    }
}

// ---------------------------------------------------------------------------
// Embedding (fp32 residual)
// ---------------------------------------------------------------------------
__global__ void embed_k(const int* __restrict__ ids,
                        const float* __restrict__ tok,
                        const float* __restrict__ pos,
                        const float* __restrict__ ctx,
                        float* __restrict__ x) {
    const int bt = blockIdx.x;
    const int b  = bt / TT;
    const int t  = bt - b * TT;
    const int id = ids[bt];
    const int d  = threadIdx.x * 4;
    const float4 a = *(const float4*)(tok + (size_t)id * DM + d);
    const float4 p = *(const float4*)(pos + (size_t)t  * DM + d);
    const float4 c = *(const float4*)(ctx + (size_t)b  * DM + d);
    float4 r;
    r.x = a.x + p.x + c.x; r.y = a.y + p.y + c.y;
    r.z = a.z + p.z + c.z; r.w = a.w + p.w + c.w;
    *(float4*)(x + (size_t)bt * DM + d) = r;
}

// ---------------------------------------------------------------------------
// LayerNorm: fp32 in -> bf16 hi/lo planes out
// ---------------------------------------------------------------------------
__global__ void layernorm_split_k(const float* __restrict__ xin,
                                  __nv_bfloat16* __restrict__ yhi,
                                  __nv_bfloat16* __restrict__ ylo,
                                  const float* __restrict__ w,
                                  const float* __restrict__ b) {
    const size_t row = blockIdx.x;
    const float* xr = xin + row * DM;
    const int d = threadIdx.x * 4;

    const float4 v = *(const float4*)(xr + d);
    float s  = v.x + v.y + v.z + v.w;
    float s2 = v.x*v.x + v.y*v.y + v.z*v.z + v.w*v.w;
    s  = block_reduce<false>(s);
    s2 = block_reduce<false>(s2);
    const float mean = s * (1.0f / DM);
    const float var  = s2 * (1.0f / DM) - mean * mean;
    const float rstd = rsqrtf(var + 1e-5f);

    const float4 ww = *(const float4*)(w + d);
    const float4 bb = *(const float4*)(b + d);
    float o0 = (v.x - mean) * rstd * ww.x + bb.x;
    float o1 = (v.y - mean) * rstd * ww.y + bb.y;
    float o2 = (v.z - mean) * rstd * ww.z + bb.z;
    float o3 = (v.w - mean) * rstd * ww.w + bb.w;
    __nv_bfloat16 h0,h1,h2,h3,l0,l1,l2,l3;
    split1(o0,h0,l0); split1(o1,h1,l1); split1(o2,h2,l2); split1(o3,h3,l3);
    __nv_bfloat162* ph = (__nv_bfloat162*)(yhi + row * DM + d);
    __nv_bfloat162* pl = (__nv_bfloat162*)(ylo + row * DM + d);
    ph[0] = __halves2bfloat162(h0,h1); ph[1] = __halves2bfloat162(h2,h3);
    pl[0] = __halves2bfloat162(l0,l1); pl[1] = __halves2bfloat162(l2,l3);
}

// ---------------------------------------------------------------------------
// Causal softmax: fp32 scores in -> bf16 hi/lo P planes out (zeros above diag)
// ---------------------------------------------------------------------------
__global__ void softmax_split_k(const float* __restrict__ S,
                                __nv_bfloat16* __restrict__ Phi,
                                __nv_bfloat16* __restrict__ Plo) {
    const int  i = blockIdx.x;
    const long z = blockIdx.y;
    const size_t roff = ((size_t)z * TT + i) * TT;
    const float* row = S + roff;
    const int len = i + 1;

    float m = -3.4e38f;
    for (int j = threadIdx.x; j < len; j += blockDim.x) m = fmaxf(m, row[j]);
    m = block_reduce<true>(m);

    float s = 0.0f;
    for (int j = threadIdx.x; j < len; j += blockDim.x) s += __expf(row[j] - m);
    s = block_reduce<false>(s);
    const float inv = 1.0f / s;

    for (int j = threadIdx.x; j < len; j += blockDim.x) {
        float p = __expf(row[j] - m) * inv;
        __nv_bfloat16 h, l; split1(p, h, l);
        Phi[roff + j] = h; Plo[roff + j] = l;
    }
    const __nv_bfloat16 zz = __float2bfloat16(0.0f);
    for (int j = len + threadIdx.x; j < TT; j += blockDim.x) {
        Phi[roff + j] = zz; Plo[roff + j] = zz;
    }
}

// ---------------------------------------------------------------------------
// Tensor-core GEMM, bf16x3 split emulation of fp32.
//   C[m,n] = epilogue( scale * sum_k A[m,k] * B(n,k) )
//   Operands are pre-split bf16 hi/lo planes.
//   BTR=true : B(n,k) = B[n*ldb+k]  (K-major; weights / K matrix)
//   BTR=false: B(n,k) = B[k*ldb+n]  (N-major; V in P@V), BN=64
//   OUT: 0 = fp32 C (+ optional residual), 1 = split bf16 planes Chi/Clo
// Pipeline: 3-stage cp.async, ldmatrix fragment loads, 8 warps (2m x 4n),
// warp tile 64 x (NT*8). Padded smem rows (80B / 144B) => conflict-free LDSM.
// ---------------------------------------------------------------------------
template <int BM, int BN, bool BTR, int OUT, bool DOGELU>
__global__ __launch_bounds__(256, 1)
void tgemm_k(const __nv_bfloat16* __restrict__ Ahi, const __nv_bfloat16* __restrict__ Alo,
             long lda, long sAb, long sAh,
             const __nv_bfloat16* __restrict__ Bhi, const __nv_bfloat16* __restrict__ Blo,
             long ldb, long sBb, long sBh,
             float* __restrict__ C,
             __nv_bfloat16* __restrict__ Chi, __nv_bfloat16* __restrict__ Clo,
             long ldc, long sCb, long sCh,
             int M, int N, int K, int nheads,
             const float* __restrict__ bias,
             const float* __restrict__ resid,
             float scale, int causal) {
    constexpr int STAGES = 3;
    constexpr int MT = 4;                    // m16 tiles per warp (warp M = 64)
    constexpr int NT = BN / 8 / 4;           // n8 tiles per warp  (4 warps in N)
    constexpr int SA = 2 * BM * 80;          // A: 2 planes, BM rows x 80B
    constexpr int SB = BTR ? (2 * BN * 80) : (2 * 32 * 144);
    constexpr int STAGE = SA + SB;
    static_assert(BM == 128, "BM=128 assumed by staging");

    extern __shared__ char smem[];
    const unsigned sb = (unsigned)__cvta_generic_to_shared(smem);

    const int z  = blockIdx.z;
    const int bb = z / nheads;
    const int hh = z - bb * nheads;
    Ahi += (size_t)bb * sAb + (size_t)hh * sAh;
    Alo += (size_t)bb * sAb + (size_t)hh * sAh;
    Bhi += (size_t)bb * sBb + (size_t)hh * sBh;
    Blo += (size_t)bb * sBb + (size_t)hh * sBh;
    const size_t coff = (size_t)bb * sCb + (size_t)hh * sCh;

    // tile raster swizzle: groups of 8 m-blocks (gridDim.y always % 8 == 0)
    const int gx  = gridDim.x;
    const int lin = blockIdx.y * gx + blockIdx.x;
    const int per = 8 * gx;
    const int bm  = (lin / per) * 8 + (lin % 8);
    const int bn  = (lin % per) / 8;
    const int m0 = bm * BM;
    const int n0 = bn * BN;
    if (causal == 1 && n0 > m0 + BM - 1) return;
    const int Keff = (causal == 2) ? min(K, m0 + BM) : K;
    const int nIt  = Keff / 32;

    const int tid  = threadIdx.x;
    const int warp = tid >> 5;
    const int lane = tid & 31;
    const int wm   = warp & 1;
    const int wn   = warp >> 1;
    const int l8   = lane & 7;
    const int g    = lane >> 3;

    float acc[MT][NT][4];
#pragma unroll
    for (int i = 0; i < MT; i++)
#pragma unroll
        for (int j = 0; j < NT; j++)
#pragma unroll
            for (int q = 0; q < 4; q++) acc[i][j][q] = 0.0f;

    // ---------------- cp.async stage issue ----------------
    auto issue = [&](int stg) {
        const unsigned sOff = sb + (stg % STAGES) * STAGE;
        const long kk = (long)stg * 32;
#pragma unroll
        for (int i = 0; i < 4; i++) {                     // A: 1024 chunks
            const int q  = tid + i * 256;
            const int pl = q >> 9;
            const int rr = (q >> 2) & 127;
            const int c  = q & 3;
            const __nv_bfloat16* gp =
                (pl ? Alo : Ahi) + (size_t)(m0 + rr) * lda + kk + c * 8;
            cp16(sOff + (unsigned)((pl * 128 + rr) * 80 + c * 16), gp);
        }
        if (BTR) {
#pragma unroll
            for (int i = 0; i < 4; i++) {                 // B: 1024 chunks
                const int q  = tid + i * 256;
                const int pl = q >> 9;
                const int rr = (q >> 2) & 127;
                const int c  = q & 3;
                const __nv_bfloat16* gp =
                    (pl ? Blo : Bhi) + (size_t)(n0 + rr) * ldb + kk + c * 8;
                cp16(sOff + (unsigned)(SA + (pl * BN + rr) * 80 + c * 16), gp);
            }
        } else {
#pragma unroll
            for (int i = 0; i < 2; i++) {                 // B: 512 chunks (32k x 64n)
                const int q  = tid + i * 256;
                const int pl = q >> 8;
                const int rr = (q >> 3) & 31;
                const int c  = q & 7;
                const __nv_bfloat16* gp =
                    (pl ? Blo : Bhi) + (size_t)(kk + rr) * ldb + n0 + c * 8;
                cp16(sOff + (unsigned)(SA + (pl * 32 + rr) * 144 + c * 16), gp);
            }
        }
    };

    // ---------------- compute one 32-k stage ----------------
    const int aRow = (g & 1) * 8 + l8;   // row-within-tile for ldmatrix lane
    const int aCh  = g >> 1;             // chunk-half for ldmatrix lane

    auto compute = [&](int buf) {
        const unsigned sA0 = sb + buf * STAGE;
        const unsigned sB0 = sA0 + SA;
#pragma unroll
        for (int s = 0; s < 2; s++) {
            unsigned a[MT][2][4];
#pragma unroll
            for (int i = 0; i < MT; i++) {
                const int m = wm * 64 + i * 16 + aRow;
                const unsigned ad = sA0 + (unsigned)(m * 80 + (2 * s + aCh) * 16);
                ldsm4(a[i][0], ad);              // hi plane
                ldsm4(a[i][1], ad + 128 * 80);   // lo plane
            }
            unsigned b[NT][2][2];
            if (BTR) {
#pragma unroll
                for (int jp = 0; jp < NT / 2; jp++) {
                    // x4: [b0_t, b1_t, b0_t+1, b1_t+1]
                    const int n = wn * (NT * 8) + jp * 16 + (g >> 1) * 8 + l8;
                    const unsigned bd = sB0 + (unsigned)(n * 80 + (2 * s + (g & 1)) * 16);
                    unsigned t[4];
                    ldsm4(t, bd);
                    b[2*jp][0][0] = t[0]; b[2*jp][0][1] = t[1];
                    b[2*jp+1][0][0] = t[2]; b[2*jp+1][0][1] = t[3];
                    ldsm4(t, bd + BN * 80);
                    b[2*jp][1][0] = t[0]; b[2*jp][1][1] = t[1];
                    b[2*jp+1][1][0] = t[2]; b[2*jp+1][1][1] = t[3];
                }
            } else {
                // PV: NT == 2, one trans-x4 per plane covers both n-tiles
                const int klo = 16 * s + (g & 1) * 8 + l8;
                const int ch  = wn * 2 + (g >> 1);
                const unsigned bd = sB0 + (unsigned)(klo * 144 + ch * 16);
                unsigned t[4];
                ldsm4t(t, bd);
                b[0][0][0] = t[0]; b[0][0][1] = t[1];
                b[1][0][0] = t[2]; b[1][0][1] = t[3];
                ldsm4t(t, bd + 32 * 144);
                b[0][1][0] = t[0]; b[0][1][1] = t[1];
                b[1][1][0] = t[2]; b[1][1][1] = t[3];
            }
#pragma unroll
            for (int i = 0; i < MT; i++)
#pragma unroll
                for (int j = 0; j < NT; j++) {
                    mma16816(acc[i][j], a[i][0], b[j][0]);   // hi*hi
                    mma16816(acc[i][j], a[i][0], b[j][1]);   // hi*lo
                    mma16816(acc[i][j], a[i][1], b[j][0]);   // lo*hi
                }
        }
    };

    // ---------------- pipelined mainloop ----------------
#pragma unroll
    for (int s = 0; s < STAGES - 1; s++) {
        if (s < nIt) issue(s);
        cp_commit();
    }
    cp_wait<STAGES - 2>();
    __syncthreads();

    for (int it = 0; it < nIt; it++) {
        const int ls = it + STAGES - 1;
        if (ls < nIt) issue(ls);
        cp_commit();
        compute(it % STAGES);
        if (it + 1 < nIt) {
            cp_wait<STAGES - 2>();
            __syncthreads();
        }
    }
    cp_wait<0>();

    // ---------------- epilogue ----------------
#pragma unroll
    for (int i = 0; i < MT; i++) {
        const int row = m0 + wm * 64 + i * 16 + (lane >> 2);
#pragma unroll
        for (int j = 0; j < NT; j++) {
            const int col = n0 + wn * (NT * 8) + j * 8 + ((lane & 3) << 1);
            float b0 = 0.f, b1 = 0.f;
            if (bias) { b0 = bias[col]; b1 = bias[col + 1]; }
#pragma unroll
            for (int hlf = 0; hlf < 2; hlf++) {
                const int r = row + hlf * 8;
                float v0 = acc[i][j][hlf * 2 + 0] * scale + b0;
                float v1 = acc[i][j][hlf * 2 + 1] * scale + b1;
                if (DOGELU) { v0 = gelu_exact(v0); v1 = gelu_exact(v1); }
                const size_t idx = coff + (size_t)r * ldc + col;
                if (OUT == 0) {
                    if (resid) {
                        const float2 rr = *(const float2*)(resid + idx);
                        v0 += rr.x; v1 += rr.y;
                    }
                    float2 o; o.x = v0; o.y = v1;
                    *(float2*)(C + idx) = o;
                } else {
                    __nv_bfloat16 h0, h1, l0, l1;
                    split1(v0, h0, l0); split1(v1, h1, l1);
                    *(__nv_bfloat162*)(Chi + idx) = __halves2bfloat162(h0, h1);
                    *(__nv_bfloat162*)(Clo + idx) = __halves2bfloat162(l0, l1);
                }
            }
        }
    }
}

// ---------------------------------------------------------------------------
// Host orchestration
// ---------------------------------------------------------------------------
extern "C" void kernel_launch(void* const* d_in, const int* in_sizes, int n_in,
                              void* d_out, int out_size) {
    (void)in_sizes; (void)n_in; (void)out_size;
    const int*   ids   = (const int*)  d_in[0];
    const float* ctx   = (const float*)d_in[1];
    const float* tok   = (const float*)d_in[2];
    const float* pos   = (const float*)d_in[3];
    const float* qkvw  = (const float*)d_in[4];
    const float* qkvb  = (const float*)d_in[5];
    const float* projw = (const float*)d_in[6];
    const float* projb = (const float*)d_in[7];
    const float* ln1w  = (const float*)d_in[8];
    const float* ln1b  = (const float*)d_in[9];
    const float* ln2w  = (const float*)d_in[10];
    const float* ln2b  = (const float*)d_in[11];
    const float* f1w   = (const float*)d_in[12];
    const float* f1b   = (const float*)d_in[13];
    const float* f2w   = (const float*)d_in[14];
    const float* f2b   = (const float*)d_in[15];
    const float* lnfw  = (const float*)d_in[16];
    const float* lnfb  = (const float*)d_in[17];
    float* out = (float*)d_out;

    float *x, *sc;
    __nv_bfloat16 *hhi,*hlo,*qhi,*qlo,*ahi,*alo,*mhi,*mlo,*phi,*plo,*whi,*wlo;
    cudaGetSymbolAddress((void**)&x,   g_x);
    cudaGetSymbolAddress((void**)&sc,  g_sc);
    cudaGetSymbolAddress((void**)&hhi, g_h_hi);   cudaGetSymbolAddress((void**)&hlo, g_h_lo);
    cudaGetSymbolAddress((void**)&qhi, g_qkv_hi); cudaGetSymbolAddress((void**)&qlo, g_qkv_lo);
    cudaGetSymbolAddress((void**)&ahi, g_at_hi);  cudaGetSymbolAddress((void**)&alo, g_at_lo);
    cudaGetSymbolAddress((void**)&mhi, g_mid_hi); cudaGetSymbolAddress((void**)&mlo, g_mid_lo);
    cudaGetSymbolAddress((void**)&phi, g_p_hi);   cudaGetSymbolAddress((void**)&plo, g_p_lo);
    cudaGetSymbolAddress((void**)&whi, g_w_hi);   cudaGetSymbolAddress((void**)&wlo, g_w_lo);

    auto kF32  = tgemm_k<128,128,true ,0,false>;   // fp32 out (+resid)
    auto kSPL  = tgemm_k<128,128,true ,1,false>;   // split out
    auto kSPLG = tgemm_k<128,128,true ,1,true >;   // split out + GELU
    auto kPV   = tgemm_k<128, 64,false,1,false>;   // P @ V, split out

    const int SM_NT = 3 * (2*128*80 + 2*128*80);   // 122880
    const int SM_PV = 3 * (2*128*80 + 2*32*144);   //  89088
    cudaFuncSetAttribute(kF32,  cudaFuncAttributeMaxDynamicSharedMemorySize, SM_NT);
    cudaFuncSetAttribute(kSPL,  cudaFuncAttributeMaxDynamicSharedMemorySize, SM_NT);
    cudaFuncSetAttribute(kSPLG, cudaFuncAttributeMaxDynamicSharedMemorySize, SM_NT);
    cudaFuncSetAttribute(kPV,   cudaFuncAttributeMaxDynamicSharedMemorySize, SM_PV);

    // ---- split all weights into bf16 hi/lo planes ----
    split_k<<<2048, 256>>>(qkvw,  whi + QW_OFF, wlo + QW_OFF, (long)(QW_SZ / 4));
    split_k<<<2048, 256>>>(projw, whi + PW_OFF, wlo + PW_OFF, (long)(PW_SZ / 4));
    split_k<<<2048, 256>>>(f1w,   whi + F1_OFF, wlo + F1_OFF, (long)(F1_SZ / 4));
    split_k<<<2048, 256>>>(f2w,   whi + F2_OFF, wlo + F2_OFF, (long)(F2_SZ / 4));
    split_k<<<2048, 256>>>(tok,   whi + TK_OFF, wlo + TK_OFF, (long)(TK_SZ / 4));

    const float attn_scale = 0.125f;   // 1/sqrt(64)

    embed_k<<<BTOK, 256>>>(ids, tok, pos, ctx, x);

    for (int l = 0; l < LAYERS; l++) {
        layernorm_split_k<<<BTOK, 256>>>(x, hhi, hlo,
                                         ln1w + (size_t)l*DM, ln1b + (size_t)l*DM);

        // qkv = h @ qkv_w^T + qkv_b  -> split planes
        kSPL<<<dim3(24, 32, 1), 256, SM_NT>>>(
            hhi, hlo, DM, 0, 0,
            whi + QW_OFF + (size_t)l*3*DM*DM, wlo + QW_OFF + (size_t)l*3*DM*DM, DM, 0, 0,
            nullptr, qhi, qlo, 3*DM, 0, 0,
            BTOK, 3*DM, DM, 1,
            qkvb + (size_t)l*3*DM, nullptr, 1.0f, 0);

        // scores = scale * Q @ K^T (fp32, skip upper-triangle tiles)
        kF32<<<dim3(16, 16, BBATCH*NH), 256, SM_NT>>>(
            qhi,      qlo,      3*DM, (long)TT*3*DM, HDIM,
            qhi + DM, qlo + DM, 3*DM, (long)TT*3*DM, HDIM,
            sc, nullptr, nullptr, TT, (long)NH*TT*TT, (long)TT*TT,
            TT, TT, HDIM, NH,
            nullptr, nullptr, attn_scale, 1);

        softmax_split_k<<<dim3(TT, BBATCH*NH), 256>>>(sc, phi, plo);

        // attn = P @ V  (K clipped to m0+128) -> split planes
        kPV<<<dim3(1, 16, BBATCH*NH), 256, SM_PV>>>(
            phi, plo, TT, (long)NH*TT*TT, (long)TT*TT,
            qhi + 2*DM, qlo + 2*DM, 3*DM, (long)TT*3*DM, HDIM,
            nullptr, ahi, alo, DM, (long)TT*DM, HDIM,
            TT, HDIM, TT, NH,
            nullptr, nullptr, 1.0f, 2);

        // x += attn @ proj_w^T + proj_b  (fp32 + residual)
        kF32<<<dim3(8, 32, 1), 256, SM_NT>>>(
            ahi, alo, DM, 0, 0,
            whi + PW_OFF + (size_t)l*DM*DM, wlo + PW_OFF + (size_t)l*DM*DM, DM, 0, 0,
            x, nullptr, nullptr, DM, 0, 0,
            BTOK, DM, DM, 1,
            projb + (size_t)l*DM, x, 1.0f, 0);

        layernorm_split_k<<<BTOK, 256>>>(x, hhi, hlo,
                                         ln2w + (size_t)l*DM, ln2b + (size_t)l*DM);

        // mid = gelu(h @ f1_w^T + f1_b) -> split planes
        kSPLG<<<dim3(32, 32, 1), 256, SM_NT>>>(
            hhi, hlo, DM, 0, 0,
            whi + F1_OFF + (size_t)l*4*DM*DM, wlo + F1_OFF + (size_t)l*4*DM*DM, DM, 0, 0,
            nullptr, mhi, mlo, 4*DM, 0, 0,
            BTOK, 4*DM, DM, 1,
            f1b + (size_t)l*4*DM, nullptr, 1.0f, 0);

        // x += mid @ f2_w^T + f2_b  (fp32 + residual)
        kF32<<<dim3(8, 32, 1), 256, SM_NT>>>(
            mhi, mlo, 4*DM, 0, 0,
            whi + F2_OFF + (size_t)l*DM*4*DM, wlo + F2_OFF + (size_t)l*DM*4*DM, 4*DM, 0, 0,
            x, nullptr, nullptr, DM, 0, 0,
            BTOK, DM, 4*DM, 1,
            f2b + (size_t)l*DM, x, 1.0f, 0);
    }

    layernorm_split_k<<<BTOK, 256>>>(x, hhi, hlo, lnfw, lnfb);

    // logits = h @ tok_emb^T (fp32)
    kF32<<<dim3(250, 32, 1), 256, SM_NT>>>(
        hhi, hlo, DM, 0, 0,
        whi + TK_OFF, wlo + TK_OFF, DM, 0, 0,
        out, nullptr, nullptr, VO, 0, 0,
        BTOK, VO, DM, 1,
        nullptr, nullptr, 1.0f, 0);
}

// round 13
// speedup vs baseline: 2.1162x; 1.0001x over previous
#include <cuda_runtime.h>
#include <cuda_bf16.h>
#include <math.h>

// ---------------------------------------------------------------------------
// Problem constants
// ---------------------------------------------------------------------------
#define LAYERS 4
#define NH     16
#define DM     1024
#define VO     32000
#define TT     2048
#define BBATCH 2
#define HDIM   64
#define BTOK   (BBATCH*TT)   // 4096

// weight-plane offsets (elements)
#define QW_SZ  ((size_t)LAYERS*3*DM*DM)      // 12,582,912
#define PW_SZ  ((size_t)LAYERS*DM*DM)        //  4,194,304
#define F1_SZ  ((size_t)LAYERS*4*DM*DM)      // 16,777,216
#define F2_SZ  ((size_t)LAYERS*4*DM*DM)      // 16,777,216
#define TK_SZ  ((size_t)VO*DM)               // 32,768,000
#define QW_OFF ((size_t)0)
#define PW_OFF (QW_OFF+QW_SZ)
#define F1_OFF (PW_OFF+PW_SZ)
#define F2_OFF (F1_OFF+F1_SZ)
#define TK_OFF (F2_OFF+F2_SZ)
#define W_TOTAL (TK_OFF+TK_SZ)

// ---------------------------------------------------------------------------
// Scratch (static __device__ arrays: the sanctioned no-alloc path)
// ---------------------------------------------------------------------------
__device__ float g_x [(size_t)BTOK * DM];                 // residual (fp32)
__device__ float g_sc[(size_t)BBATCH * NH * TT * TT];     // scores   (fp32)

__device__ __nv_bfloat16 g_h_hi  [(size_t)BTOK * DM];
__device__ __nv_bfloat16 g_h_lo  [(size_t)BTOK * DM];
__device__ __nv_bfloat16 g_qkv_hi[(size_t)BTOK * 3 * DM];
__device__ __nv_bfloat16 g_qkv_lo[(size_t)BTOK * 3 * DM];
__device__ __nv_bfloat16 g_at_hi [(size_t)BTOK * DM];
__device__ __nv_bfloat16 g_at_lo [(size_t)BTOK * DM];
__device__ __nv_bfloat16 g_mid_hi[(size_t)BTOK * 4 * DM];
__device__ __nv_bfloat16 g_mid_lo[(size_t)BTOK * 4 * DM];
__device__ __nv_bfloat16 g_p_hi  [(size_t)BBATCH * NH * TT * TT];
__device__ __nv_bfloat16 g_p_lo  [(size_t)BBATCH * NH * TT * TT];
__device__ __nv_bfloat16 g_w_hi  [W_TOTAL];
__device__ __nv_bfloat16 g_w_lo  [W_TOTAL];

// ---------------------------------------------------------------------------
// Small helpers
// ---------------------------------------------------------------------------
__device__ __forceinline__ float gelu_exact(float x) {
    return 0.5f * x * (1.0f + erff(x * 0.70710678118654752440f));
}
__device__ __forceinline__ void split1(float v, __nv_bfloat16& h, __nv_bfloat16& l) {
    h = __float2bfloat16(v);
    l = __float2bfloat16(v - __bfloat162float(h));
}

template <bool DOMAX>
__device__ __forceinline__ float block_reduce(float v) {
    __shared__ float sh[33];
    const int lane = threadIdx.x & 31;
    const int wid  = threadIdx.x >> 5;
#pragma unroll
    for (int o = 16; o; o >>= 1) {
        float t = __shfl_xor_sync(0xffffffffu, v, o);
        v = DOMAX ? fmaxf(v, t) : (v + t);
    }
    if (lane == 0) sh[wid] = v;
    __syncthreads();
    const int nw = blockDim.x >> 5;
    if (wid == 0) {
        float t = (lane < nw) ? sh[lane] : (DOMAX ? -3.4e38f : 0.0f);
#pragma unroll
        for (int o = 16; o; o >>= 1) {
            float u = __shfl_xor_sync(0xffffffffu, t, o);
            t = DOMAX ? fmaxf(t, u) : (t + u);
        }
        if (lane == 0) sh[32] = t;
    }
    __syncthreads();
    float r = sh[32];
    __syncthreads();
    return r;
}

__device__ __forceinline__ void mma16816(float* c, const unsigned* a, const unsigned* b) {
    asm volatile(
        "mma.sync.aligned.m16n8k16.row.col.f32.bf16.bf16.f32 "
        "{%0,%1,%2,%3}, {%4,%5,%6,%7}, {%8,%9}, {%0,%1,%2,%3};\n"
        : "+f"(c[0]), "+f"(c[1]), "+f"(c[2]), "+f"(c[3])
        : "r"(a[0]), "r"(a[1]), "r"(a[2]), "r"(a[3]), "r"(b[0]), "r"(b[1]));
}
__device__ __forceinline__ void ldsm4(unsigned* r, unsigned a) {
    asm volatile("ldmatrix.sync.aligned.m8n8.x4.shared.b16 {%0,%1,%2,%3}, [%4];"
                 : "=r"(r[0]), "=r"(r[1]), "=r"(r[2]), "=r"(r[3]) : "r"(a));
}
__device__ __forceinline__ void ldsm4t(unsigned* r, unsigned a) {
    asm volatile("ldmatrix.sync.aligned.m8n8.x4.trans.shared.b16 {%0,%1,%2,%3}, [%4];"
                 : "=r"(r[0]), "=r"(r[1]), "=r"(r[2]), "=r"(r[3]) : "r"(a));
}
__device__ __forceinline__ void cp16(unsigned saddr, const void* g) {
    asm volatile("cp.async.cg.shared.global [%0], [%1], 16;" :: "r"(saddr), "l"(g));
}
__device__ __forceinline__ void cp_commit() { asm volatile("cp.async.commit_group;"); }
template <int N>
__device__ __forceinline__ void cp_wait() { asm volatile("cp.async.wait_group %0;" :: "n"(N)); }

// ---------------------------------------------------------------------------
// fp32 -> bf16 hi/lo split (weights)
// ---------------------------------------------------------------------------
__global__ void split_k(const float* __restrict__ s,
                        __nv_bfloat16* __restrict__ hi,
                        __nv_bfloat16* __restrict__ lo, long n4) {
    long i = (long)blockIdx.x * blockDim.x + threadIdx.x;
    const long stride = (long)gridDim.x * blockDim.x;
    for (; i < n4; i += stride) {
        float4 v = ((const float4*)s)[i];
        __nv_bfloat16 h0,h1,h2,h3,l0,l1,l2,l3;
        split1(v.x,h0,l0); split1(v.y,h1,l1); split1(v.z,h2,l2); split1(v.w,h3,l3);
        ((__nv_bfloat162*)hi)[2*i+0] = __halves2bfloat162(h0,h1);
        ((__nv_bfloat162*)hi)[2*i+1] = __halves2bfloat162(h2,h3);
        ((__nv_bfloat162*)lo)[2*i+0] = __halves2bfloat162(l0,l1);
        ((__nv_bfloat162*)lo)[2*i+1] = __halves2bfloat162(l2,l3);
    }
}

// ---------------------------------------------------------------------------
// Embedding (fp32 residual)
// ---------------------------------------------------------------------------
__global__ void embed_k(const int* __restrict__ ids,
                        const float* __restrict__ tok,
                        const float* __restrict__ pos,
                        const float* __restrict__ ctx,
                        float* __restrict__ x) {
    const int bt = blockIdx.x;
    const int b  = bt / TT;
    const int t  = bt - b * TT;
    const int id = ids[bt];
    const int d  = threadIdx.x * 4;
    const float4 a = *(const float4*)(tok + (size_t)id * DM + d);
    const float4 p = *(const float4*)(pos + (size_t)t  * DM + d);
    const float4 c = *(const float4*)(ctx + (size_t)b  * DM + d);
    float4 r;
    r.x = a.x + p.x + c.x; r.y = a.y + p.y + c.y;
    r.z = a.z + p.z + c.z; r.w = a.w + p.w + c.w;
    *(float4*)(x + (size_t)bt * DM + d) = r;
}

// ---------------------------------------------------------------------------
// LayerNorm: fp32 in -> bf16 hi/lo planes out
// ---------------------------------------------------------------------------
__global__ void layernorm_split_k(const float* __restrict__ xin,
                                  __nv_bfloat16* __restrict__ yhi,
                                  __nv_bfloat16* __restrict__ ylo,
                                  const float* __restrict__ w,
                                  const float* __restrict__ b) {
    const size_t row = blockIdx.x;
    const float* xr = xin + row * DM;
    const int d = threadIdx.x * 4;

    const float4 v = *(const float4*)(xr + d);
    float s  = v.x + v.y + v.z + v.w;
    float s2 = v.x*v.x + v.y*v.y + v.z*v.z + v.w*v.w;
    s  = block_reduce<false>(s);
    s2 = block_reduce<false>(s2);
    const float mean = s * (1.0f / DM);
    const float var  = s2 * (1.0f / DM) - mean * mean;
    const float rstd = rsqrtf(var + 1e-5f);

    const float4 ww = *(const float4*)(w + d);
    const float4 bb = *(const float4*)(b + d);
    float o0 = (v.x - mean) * rstd * ww.x + bb.x;
    float o1 = (v.y - mean) * rstd * ww.y + bb.y;
    float o2 = (v.z - mean) * rstd * ww.z + bb.z;
    float o3 = (v.w - mean) * rstd * ww.w + bb.w;
    __nv_bfloat16 h0,h1,h2,h3,l0,l1,l2,l3;
    split1(o0,h0,l0); split1(o1,h1,l1); split1(o2,h2,l2); split1(o3,h3,l3);
    __nv_bfloat162* ph = (__nv_bfloat162*)(yhi + row * DM + d);
    __nv_bfloat162* pl = (__nv_bfloat162*)(ylo + row * DM + d);
    ph[0] = __halves2bfloat162(h0,h1); ph[1] = __halves2bfloat162(h2,h3);
    pl[0] = __halves2bfloat162(l0,l1); pl[1] = __halves2bfloat162(l2,l3);
}

// ---------------------------------------------------------------------------
// Causal softmax: fp32 scores in -> bf16 hi/lo P planes out (zeros above diag)
// ---------------------------------------------------------------------------
__global__ void softmax_split_k(const float* __restrict__ S,
                                __nv_bfloat16* __restrict__ Phi,
                                __nv_bfloat16* __restrict__ Plo) {
    const int  i = blockIdx.x;
    const long z = blockIdx.y;
    const size_t roff = ((size_t)z * TT + i) * TT;
    const float* row = S + roff;
    const int len = i + 1;

    float m = -3.4e38f;
    for (int j = threadIdx.x; j < len; j += blockDim.x) m = fmaxf(m, row[j]);
    m = block_reduce<true>(m);

    float s = 0.0f;
    for (int j = threadIdx.x; j < len; j += blockDim.x) s += __expf(row[j] - m);
    s = block_reduce<false>(s);
    const float inv = 1.0f / s;

    for (int j = threadIdx.x; j < len; j += blockDim.x) {
        float p = __expf(row[j] - m) * inv;
        __nv_bfloat16 h, l; split1(p, h, l);
        Phi[roff + j] = h; Plo[roff + j] = l;
    }
    const __nv_bfloat16 zz = __float2bfloat16(0.0f);
    for (int j = len + threadIdx.x; j < TT; j += blockDim.x) {
        Phi[roff + j] = zz; Plo[roff + j] = zz;
    }
}

// ---------------------------------------------------------------------------
// Tensor-core GEMM, bf16x3 split emulation of fp32.
//   C[m,n] = epilogue( scale * sum_k A[m,k] * B(n,k) )
//   Operands are pre-split bf16 hi/lo planes.
//   BTR=true : B(n,k) = B[n*ldb+k]  (K-major; weights / K matrix)
//   BTR=false: B(n,k) = B[k*ldb+n]  (N-major; V in P@V), BN=64
//   OUT: 0 = fp32 C (+ optional residual), 1 = split bf16 planes Chi/Clo
// Pipeline: 3-stage cp.async, ldmatrix fragment loads, 8 warps (2m x 4n),
// warp tile 64 x (NT*8). Padded smem rows (80B / 144B) => conflict-free LDSM.
// ---------------------------------------------------------------------------
template <int BM, int BN, bool BTR, int OUT, bool DOGELU>
__global__ __launch_bounds__(256, 1)
void tgemm_k(const __nv_bfloat16* __restrict__ Ahi, const __nv_bfloat16* __restrict__ Alo,
             long lda, long sAb, long sAh,
             const __nv_bfloat16* __restrict__ Bhi, const __nv_bfloat16* __restrict__ Blo,
             long ldb, long sBb, long sBh,
             float* __restrict__ C,
             __nv_bfloat16* __restrict__ Chi, __nv_bfloat16* __restrict__ Clo,
             long ldc, long sCb, long sCh,
             int M, int N, int K, int nheads,
             const float* __restrict__ bias,
             const float* __restrict__ resid,
             float scale, int causal) {
    constexpr int STAGES = 3;
    constexpr int MT = 4;                    // m16 tiles per warp (warp M = 64)
    constexpr int NT = BN / 8 / 4;           // n8 tiles per warp  (4 warps in N)
    constexpr int SA = 2 * BM * 80;          // A: 2 planes, BM rows x 80B
    constexpr int SB = BTR ? (2 * BN * 80) : (2 * 32 * 144);
    constexpr int STAGE = SA + SB;
    static_assert(BM == 128, "BM=128 assumed by staging");

    extern __shared__ char smem[];
    const unsigned sb = (unsigned)__cvta_generic_to_shared(smem);

    const int z  = blockIdx.z;
    const int bb = z / nheads;
    const int hh = z - bb * nheads;
    Ahi += (size_t)bb * sAb + (size_t)hh * sAh;
    Alo += (size_t)bb * sAb + (size_t)hh * sAh;
    Bhi += (size_t)bb * sBb + (size_t)hh * sBh;
    Blo += (size_t)bb * sBb + (size_t)hh * sBh;
    const size_t coff = (size_t)bb * sCb + (size_t)hh * sCh;

    // tile raster swizzle: groups of 8 m-blocks (gridDim.y always % 8 == 0)
    const int gx  = gridDim.x;
    const int lin = blockIdx.y * gx + blockIdx.x;
    const int per = 8 * gx;
    const int bm  = (lin / per) * 8 + (lin % 8);
    const int bn  = (lin % per) / 8;
    const int m0 = bm * BM;
    const int n0 = bn * BN;
    if (causal == 1 && n0 > m0 + BM - 1) return;
    const int Keff = (causal == 2) ? min(K, m0 + BM) : K;
    const int nIt  = Keff / 32;

    const int tid  = threadIdx.x;
    const int warp = tid >> 5;
    const int lane = tid & 31;
    const int wm   = warp & 1;
    const int wn   = warp >> 1;
    const int l8   = lane & 7;
    const int g    = lane >> 3;

    float acc[MT][NT][4];
#pragma unroll
    for (int i = 0; i < MT; i++)
#pragma unroll
        for (int j = 0; j < NT; j++)
#pragma unroll
            for (int q = 0; q < 4; q++) acc[i][j][q] = 0.0f;

    // ---------------- cp.async stage issue ----------------
    auto issue = [&](int stg) {
        const unsigned sOff = sb + (stg % STAGES) * STAGE;
        const long kk = (long)stg * 32;
#pragma unroll
        for (int i = 0; i < 4; i++) {                     // A: 1024 chunks
            const int q  = tid + i * 256;
            const int pl = q >> 9;
            const int rr = (q >> 2) & 127;
            const int c  = q & 3;
            const __nv_bfloat16* gp =
                (pl ? Alo : Ahi) + (size_t)(m0 + rr) * lda + kk + c * 8;
            cp16(sOff + (unsigned)((pl * 128 + rr) * 80 + c * 16), gp);
        }
        if (BTR) {
#pragma unroll
            for (int i = 0; i < 4; i++) {                 // B: 1024 chunks
                const int q  = tid + i * 256;
                const int pl = q >> 9;
                const int rr = (q >> 2) & 127;
                const int c  = q & 3;
                const __nv_bfloat16* gp =
                    (pl ? Blo : Bhi) + (size_t)(n0 + rr) * ldb + kk + c * 8;
                cp16(sOff + (unsigned)(SA + (pl * BN + rr) * 80 + c * 16), gp);
            }
        } else {
#pragma unroll
            for (int i = 0; i < 2; i++) {                 // B: 512 chunks (32k x 64n)
                const int q  = tid + i * 256;
                const int pl = q >> 8;
                const int rr = (q >> 3) & 31;
                const int c  = q & 7;
                const __nv_bfloat16* gp =
                    (pl ? Blo : Bhi) + (size_t)(kk + rr) * ldb + n0 + c * 8;
                cp16(sOff + (unsigned)(SA + (pl * 32 + rr) * 144 + c * 16), gp);
            }
        }
    };

    // ---------------- compute one 32-k stage ----------------
    const int aRow = (g & 1) * 8 + l8;   // row-within-tile for ldmatrix lane
    const int aCh  = g >> 1;             // chunk-half for ldmatrix lane

    auto compute = [&](int buf) {
        const unsigned sA0 = sb + buf * STAGE;
        const unsigned sB0 = sA0 + SA;
#pragma unroll
        for (int s = 0; s < 2; s++) {
            unsigned a[MT][2][4];
#pragma unroll
            for (int i = 0; i < MT; i++) {
                const int m = wm * 64 + i * 16 + aRow;
                const unsigned ad = sA0 + (unsigned)(m * 80 + (2 * s + aCh) * 16);
                ldsm4(a[i][0], ad);              // hi plane
                ldsm4(a[i][1], ad + 128 * 80);   // lo plane
            }
            unsigned b[NT][2][2];
            if (BTR) {
#pragma unroll
                for (int jp = 0; jp < NT / 2; jp++) {
                    // x4: [b0_t, b1_t, b0_t+1, b1_t+1]
                    const int n = wn * (NT * 8) + jp * 16 + (g >> 1) * 8 + l8;
                    const unsigned bd = sB0 + (unsigned)(n * 80 + (2 * s + (g & 1)) * 16);
                    unsigned t[4];
                    ldsm4(t, bd);
                    b[2*jp][0][0] = t[0]; b[2*jp][0][1] = t[1];
                    b[2*jp+1][0][0] = t[2]; b[2*jp+1][0][1] = t[3];
                    ldsm4(t, bd + BN * 80);
                    b[2*jp][1][0] = t[0]; b[2*jp][1][1] = t[1];
                    b[2*jp+1][1][0] = t[2]; b[2*jp+1][1][1] = t[3];
                }
            } else {
                // PV: NT == 2, one trans-x4 per plane covers both n-tiles
                const int klo = 16 * s + (g & 1) * 8 + l8;
                const int ch  = wn * 2 + (g >> 1);
                const unsigned bd = sB0 + (unsigned)(klo * 144 + ch * 16);
                unsigned t[4];
                ldsm4t(t, bd);
                b[0][0][0] = t[0]; b[0][0][1] = t[1];
                b[1][0][0] = t[2]; b[1][0][1] = t[3];
                ldsm4t(t, bd + 32 * 144);
                b[0][1][0] = t[0]; b[0][1][1] = t[1];
                b[1][1][0] = t[2]; b[1][1][1] = t[3];
            }
#pragma unroll
            for (int i = 0; i < MT; i++)
#pragma unroll
                for (int j = 0; j < NT; j++) {
                    mma16816(acc[i][j], a[i][0], b[j][0]);   // hi*hi
                    mma16816(acc[i][j], a[i][0], b[j][1]);   // hi*lo
                    mma16816(acc[i][j], a[i][1], b[j][0]);   // lo*hi
                }
        }
    };

    // ---------------- pipelined mainloop ----------------
#pragma unroll
    for (int s = 0; s < STAGES - 1; s++) {
        if (s < nIt) issue(s);
        cp_commit();
    }
    cp_wait<STAGES - 2>();
    __syncthreads();

    for (int it = 0; it < nIt; it++) {
        const int ls = it + STAGES - 1;
        if (ls < nIt) issue(ls);
        cp_commit();
        compute(it % STAGES);
        if (it + 1 < nIt) {
            cp_wait<STAGES - 2>();
            __syncthreads();
        }
    }
    cp_wait<0>();

    // ---------------- epilogue ----------------
#pragma unroll
    for (int i = 0; i < MT; i++) {
        const int row = m0 + wm * 64 + i * 16 + (lane >> 2);
#pragma unroll
        for (int j = 0; j < NT; j++) {
            const int col = n0 + wn * (NT * 8) + j * 8 + ((lane & 3) << 1);
            float b0 = 0.f, b1 = 0.f;
            if (bias) { b0 = bias[col]; b1 = bias[col + 1]; }
#pragma unroll
            for (int hlf = 0; hlf < 2; hlf++) {
                const int r = row + hlf * 8;
                float v0 = acc[i][j][hlf * 2 + 0] * scale + b0;
                float v1 = acc[i][j][hlf * 2 + 1] * scale + b1;
                if (DOGELU) { v0 = gelu_exact(v0); v1 = gelu_exact(v1); }
                const size_t idx = coff + (size_t)r * ldc + col;
                if (OUT == 0) {
                    if (resid) {
                        const float2 rr = *(const float2*)(resid + idx);
                        v0 += rr.x; v1 += rr.y;
                    }
                    float2 o; o.x = v0; o.y = v1;
                    *(float2*)(C + idx) = o;
                } else {
                    __nv_bfloat16 h0, h1, l0, l1;
                    split1(v0, h0, l0); split1(v1, h1, l1);
                    *(__nv_bfloat162*)(Chi + idx) = __halves2bfloat162(h0, h1);
                    *(__nv_bfloat162*)(Clo + idx) = __halves2bfloat162(l0, l1);
                }
            }
        }
    }
}

// ---------------------------------------------------------------------------
// Host orchestration
// ---------------------------------------------------------------------------
extern "C" void kernel_launch(void* const* d_in, const int* in_sizes, int n_in,
                              void* d_out, int out_size) {
    (void)in_sizes; (void)n_in; (void)out_size;
    const int*   ids   = (const int*)  d_in[0];
    const float* ctx   = (const float*)d_in[1];
    const float* tok   = (const float*)d_in[2];
    const float* pos   = (const float*)d_in[3];
    const float* qkvw  = (const float*)d_in[4];
    const float* qkvb  = (const float*)d_in[5];
    const float* projw = (const float*)d_in[6];
    const float* projb = (const float*)d_in[7];
    const float* ln1w  = (const float*)d_in[8];
    const float* ln1b  = (const float*)d_in[9];
    const float* ln2w  = (const float*)d_in[10];
    const float* ln2b  = (const float*)d_in[11];
    const float* f1w   = (const float*)d_in[12];
    const float* f1b   = (const float*)d_in[13];
    const float* f2w   = (const float*)d_in[14];
    const float* f2b   = (const float*)d_in[15];
    const float* lnfw  = (const float*)d_in[16];
    const float* lnfb  = (const float*)d_in[17];
    float* out = (float*)d_out;

    float *x, *sc;
    __nv_bfloat16 *hhi,*hlo,*qhi,*qlo,*ahi,*alo,*mhi,*mlo,*phi,*plo,*whi,*wlo;
    cudaGetSymbolAddress((void**)&x,   g_x);
    cudaGetSymbolAddress((void**)&sc,  g_sc);
    cudaGetSymbolAddress((void**)&hhi, g_h_hi);   cudaGetSymbolAddress((void**)&hlo, g_h_lo);
    cudaGetSymbolAddress((void**)&qhi, g_qkv_hi); cudaGetSymbolAddress((void**)&qlo, g_qkv_lo);
    cudaGetSymbolAddress((void**)&ahi, g_at_hi);  cudaGetSymbolAddress((void**)&alo, g_at_lo);
    cudaGetSymbolAddress((void**)&mhi, g_mid_hi); cudaGetSymbolAddress((void**)&mlo, g_mid_lo);
    cudaGetSymbolAddress((void**)&phi, g_p_hi);   cudaGetSymbolAddress((void**)&plo, g_p_lo);
    cudaGetSymbolAddress((void**)&whi, g_w_hi);   cudaGetSymbolAddress((void**)&wlo, g_w_lo);

    auto kF32  = tgemm_k<128,128,true ,0,false>;   // fp32 out (+resid)
    auto kSPL  = tgemm_k<128,128,true ,1,false>;   // split out
    auto kSPLG = tgemm_k<128,128,true ,1,true >;   // split out + GELU
    auto kPV   = tgemm_k<128, 64,false,1,false>;   // P @ V, split out

    const int SM_NT = 3 * (2*128*80 + 2*128*80);   // 122880
    const int SM_PV = 3 * (2*128*80 + 2*32*144);   //  89088
    cudaFuncSetAttribute(kF32,  cudaFuncAttributeMaxDynamicSharedMemorySize, SM_NT);
    cudaFuncSetAttribute(kSPL,  cudaFuncAttributeMaxDynamicSharedMemorySize, SM_NT);
    cudaFuncSetAttribute(kSPLG, cudaFuncAttributeMaxDynamicSharedMemorySize, SM_NT);
    cudaFuncSetAttribute(kPV,   cudaFuncAttributeMaxDynamicSharedMemorySize, SM_PV);

    // ---- split all weights into bf16 hi/lo planes ----
    split_k<<<2048, 256>>>(qkvw,  whi + QW_OFF, wlo + QW_OFF, (long)(QW_SZ / 4));
    split_k<<<2048, 256>>>(projw, whi + PW_OFF, wlo + PW_OFF, (long)(PW_SZ / 4));
    split_k<<<2048, 256>>>(f1w,   whi + F1_OFF, wlo + F1_OFF, (long)(F1_SZ / 4));
    split_k<<<2048, 256>>>(f2w,   whi + F2_OFF, wlo + F2_OFF, (long)(F2_SZ / 4));
    split_k<<<2048, 256>>>(tok,   whi + TK_OFF, wlo + TK_OFF, (long)(TK_SZ / 4));

    const float attn_scale = 0.125f;   // 1/sqrt(64)

    embed_k<<<BTOK, 256>>>(ids, tok, pos, ctx, x);

    for (int l = 0; l < LAYERS; l++) {
        layernorm_split_k<<<BTOK, 256>>>(x, hhi, hlo,
                                         ln1w + (size_t)l*DM, ln1b + (size_t)l*DM);

        // qkv = h @ qkv_w^T + qkv_b  -> split planes
        kSPL<<<dim3(24, 32, 1), 256, SM_NT>>>(
            hhi, hlo, DM, 0, 0,
            whi + QW_OFF + (size_t)l*3*DM*DM, wlo + QW_OFF + (size_t)l*3*DM*DM, DM, 0, 0,
            nullptr, qhi, qlo, 3*DM, 0, 0,
            BTOK, 3*DM, DM, 1,
            qkvb + (size_t)l*3*DM, nullptr, 1.0f, 0);

        // scores = scale * Q @ K^T (fp32, skip upper-triangle tiles)
        kF32<<<dim3(16, 16, BBATCH*NH), 256, SM_NT>>>(
            qhi,      qlo,      3*DM, (long)TT*3*DM, HDIM,
            qhi + DM, qlo + DM, 3*DM, (long)TT*3*DM, HDIM,
            sc, nullptr, nullptr, TT, (long)NH*TT*TT, (long)TT*TT,
            TT, TT, HDIM, NH,
            nullptr, nullptr, attn_scale, 1);

        softmax_split_k<<<dim3(TT, BBATCH*NH), 256>>>(sc, phi, plo);

        // attn = P @ V  (K clipped to m0+128) -> split planes
        kPV<<<dim3(1, 16, BBATCH*NH), 256, SM_PV>>>(
            phi, plo, TT, (long)NH*TT*TT, (long)TT*TT,
            qhi + 2*DM, qlo + 2*DM, 3*DM, (long)TT*3*DM, HDIM,
            nullptr, ahi, alo, DM, (long)TT*DM, HDIM,
            TT, HDIM, TT, NH,
            nullptr, nullptr, 1.0f, 2);

        // x += attn @ proj_w^T + proj_b  (fp32 + residual)
        kF32<<<dim3(8, 32, 1), 256, SM_NT>>>(
            ahi, alo, DM, 0, 0,
            whi + PW_OFF + (size_t)l*DM*DM, wlo + PW_OFF + (size_t)l*DM*DM, DM, 0, 0,
            x, nullptr, nullptr, DM, 0, 0,
            BTOK, DM, DM, 1,
            projb + (size_t)l*DM, x, 1.0f, 0);

        layernorm_split_k<<<BTOK, 256>>>(x, hhi, hlo,
                                         ln2w + (size_t)l*DM, ln2b + (size_t)l*DM);

        // mid = gelu(h @ f1_w^T + f1_b) -> split planes
        kSPLG<<<dim3(32, 32, 1), 256, SM_NT>>>(
            hhi, hlo, DM, 0, 0,
            whi + F1_OFF + (size_t)l*4*DM*DM, wlo + F1_OFF + (size_t)l*4*DM*DM, DM, 0, 0,
            nullptr, mhi, mlo, 4*DM, 0, 0,
            BTOK, 4*DM, DM, 1,
            f1b + (size_t)l*4*DM, nullptr, 1.0f, 0);

        // x += mid @ f2_w^T + f2_b  (fp32 + residual)
        kF32<<<dim3(8, 32, 1), 256, SM_NT>>>(
            mhi, mlo, 4*DM, 0, 0,
            whi + F2_OFF + (size_t)l*DM*4*DM, wlo + F2_OFF + (size_t)l*DM*4*DM, 4*DM, 0, 0,
            x, nullptr, nullptr, DM, 0, 0,
            BTOK, DM, 4*DM, 1,
            f2b + (size_t)l*DM, x, 1.0f, 0);
    }

    layernorm_split_k<<<BTOK, 256>>>(x, hhi, hlo, lnfw, lnfb);

    // logits = h @ tok_emb^T (fp32)
    kF32<<<dim3(250, 32, 1), 256, SM_NT>>>(
        hhi, hlo, DM, 0, 0,
        whi + TK_OFF, wlo + TK_OFF, DM, 0, 0,
        out, nullptr, nullptr, VO, 0, 0,
        BTOK, VO, DM, 1,
        nullptr, nullptr, 1.0f, 0);
}

// round 15
// speedup vs baseline: 2.6992x; 1.2755x over previous
#include <cuda_runtime.h>
#include <cuda_bf16.h>
#include <math.h>

// ---------------------------------------------------------------------------
// Problem constants
// ---------------------------------------------------------------------------
#define LAYERS 4
#define NH     16
#define DM     1024
#define VO     32000
#define TT     2048
#define BBATCH 2
#define HDIM   64
#define BTOK   (BBATCH*TT)   // 4096

// weight-plane offsets (elements)
#define QW_SZ  ((size_t)LAYERS*3*DM*DM)
#define PW_SZ  ((size_t)LAYERS*DM*DM)
#define F1_SZ  ((size_t)LAYERS*4*DM*DM)
#define F2_SZ  ((size_t)LAYERS*4*DM*DM)
#define TK_SZ  ((size_t)VO*DM)
#define QW_OFF ((size_t)0)
#define PW_OFF (QW_OFF+QW_SZ)
#define F1_OFF (PW_OFF+PW_SZ)
#define F2_OFF (F1_OFF+F1_SZ)
#define TK_OFF (F2_OFF+F2_SZ)
#define W_TOTAL (TK_OFF+TK_SZ)

// ---------------------------------------------------------------------------
// Scratch (static __device__ arrays: the sanctioned no-alloc path)
// ---------------------------------------------------------------------------
__device__ float g_x [(size_t)BTOK * DM];
__device__ float g_sc[(size_t)BBATCH * NH * TT * TT];

__device__ __nv_bfloat16 g_h_hi  [(size_t)BTOK * DM];
__device__ __nv_bfloat16 g_h_lo  [(size_t)BTOK * DM];
__device__ __nv_bfloat16 g_qkv_hi[(size_t)BTOK * 3 * DM];
__device__ __nv_bfloat16 g_qkv_lo[(size_t)BTOK * 3 * DM];
__device__ __nv_bfloat16 g_at_hi [(size_t)BTOK * DM];
__device__ __nv_bfloat16 g_at_lo [(size_t)BTOK * DM];
__device__ __nv_bfloat16 g_mid_hi[(size_t)BTOK * 4 * DM];
__device__ __nv_bfloat16 g_mid_lo[(size_t)BTOK * 4 * DM];
__device__ __nv_bfloat16 g_p_hi  [(size_t)BBATCH * NH * TT * TT];
__device__ __nv_bfloat16 g_p_lo  [(size_t)BBATCH * NH * TT * TT];
__device__ __nv_bfloat16 g_w_hi  [W_TOTAL];
__device__ __nv_bfloat16 g_w_lo  [W_TOTAL];

// ---------------------------------------------------------------------------
// Small helpers
// ---------------------------------------------------------------------------
__device__ __forceinline__ float gelu_exact(float x) {
    return 0.5f * x * (1.0f + erff(x * 0.70710678118654752440f));
}
__device__ __forceinline__ void split1(float v, __nv_bfloat16& h, __nv_bfloat16& l) {
    h = __float2bfloat16(v);
    l = __float2bfloat16(v - __bfloat162float(h));
}

template <bool DOMAX>
__device__ __forceinline__ float block_reduce(float v) {
    __shared__ float sh[33];
    const int lane = threadIdx.x & 31;
    const int wid  = threadIdx.x >> 5;
#pragma unroll
    for (int o = 16; o; o >>= 1) {
        float t = __shfl_xor_sync(0xffffffffu, v, o);
        v = DOMAX ? fmaxf(v, t) : (v + t);
    }
    if (lane == 0) sh[wid] = v;
    __syncthreads();
    const int nw = blockDim.x >> 5;
    if (wid == 0) {
        float t = (lane < nw) ? sh[lane] : (DOMAX ? -3.4e38f : 0.0f);
#pragma unroll
        for (int o = 16; o; o >>= 1) {
            float u = __shfl_xor_sync(0xffffffffu, t, o);
            t = DOMAX ? fmaxf(t, u) : (t + u);
        }
        if (lane == 0) sh[32] = t;
    }
    __syncthreads();
    float r = sh[32];
    __syncthreads();
    return r;
}

__device__ __forceinline__ void mma16816(float* c, const unsigned* a, const unsigned* b) {
    asm volatile(
        "mma.sync.aligned.m16n8k16.row.col.f32.bf16.bf16.f32 "
        "{%0,%1,%2,%3}, {%4,%5,%6,%7}, {%8,%9}, {%0,%1,%2,%3};\n"
        : "+f"(c[0]), "+f"(c[1]), "+f"(c[2]), "+f"(c[3])
        : "r"(a[0]), "r"(a[1]), "r"(a[2]), "r"(a[3]), "r"(b[0]), "r"(b[1]));
}
__device__ __forceinline__ void ldsm4(unsigned* r, unsigned a) {
    asm volatile("ldmatrix.sync.aligned.m8n8.x4.shared.b16 {%0,%1,%2,%3}, [%4];"
                 : "=r"(r[0]), "=r"(r[1]), "=r"(r[2]), "=r"(r[3]) : "r"(a));
}
__device__ __forceinline__ void ldsm4t(unsigned* r, unsigned a) {
    asm volatile("ldmatrix.sync.aligned.m8n8.x4.trans.shared.b16 {%0,%1,%2,%3}, [%4];"
                 : "=r"(r[0]), "=r"(r[1]), "=r"(r[2]), "=r"(r[3]) : "r"(a));
}
__device__ __forceinline__ void cp16(unsigned saddr, const void* g) {
    asm volatile("cp.async.cg.shared.global [%0], [%1], 16;" :: "r"(saddr), "l"(g));
}
__device__ __forceinline__ void cp_commit() { asm volatile("cp.async.commit_group;"); }
template <int N>
__device__ __forceinline__ void cp_wait() { asm volatile("cp.async.wait_group %0;" :: "n"(N)); }

// ---------------------------------------------------------------------------
// fp32 -> bf16 hi/lo split (weights)
// ---------------------------------------------------------------------------
__global__ void split_k(const float* __restrict__ s,
                        __nv_bfloat16* __restrict__ hi,
                        __nv_bfloat16* __restrict__ lo, long n4) {
    long i = (long)blockIdx.x * blockDim.x + threadIdx.x;
    const long stride = (long)gridDim.x * blockDim.x;
    for (; i < n4; i += stride) {
        float4 v = ((const float4*)s)[i];
        __nv_bfloat16 h0,h1,h2,h3,l0,l1,l2,l3;
        split1(v.x,h0,l0); split1(v.y,h1,l1); split1(v.z,h2,l2); split1(v.w,h3,l3);
        ((__nv_bfloat162*)hi)[2*i+0] = __halves2bfloat162(h0,h1);
        ((__nv_bfloat162*)hi)[2*i+1] = __halves2bfloat162(h2,h3);
        ((__nv_bfloat162*)lo)[2*i+0] = __halves2bfloat162(l0,l1);
        ((__nv_bfloat162*)lo)[2*i+1] = __halves2bfloat162(l2,l3);
    }
}

// ---------------------------------------------------------------------------
// Embedding (fp32 residual)
// ---------------------------------------------------------------------------
__global__ void embed_k(const int* __restrict__ ids,
                        const float* __restrict__ tok,
                        const float* __restrict__ pos,
                        const float* __restrict__ ctx,
                        float* __restrict__ x) {
    const int bt = blockIdx.x;
    const int b  = bt / TT;
    const int t  = bt - b * TT;
    const int id = ids[bt];
    const int d  = threadIdx.x * 4;
    const float4 a = *(const float4*)(tok + (size_t)id * DM + d);
    const float4 p = *(const float4*)(pos + (size_t)t  * DM + d);
    const float4 c = *(const float4*)(ctx + (size_t)b  * DM + d);
    float4 r;
    r.x = a.x + p.x + c.x; r.y = a.y + p.y + c.y;
    r.z = a.z + p.z + c.z; r.w = a.w + p.w + c.w;
    *(float4*)(x + (size_t)bt * DM + d) = r;
}

// ---------------------------------------------------------------------------
// LayerNorm: fp32 in -> bf16 hi/lo planes out
// ---------------------------------------------------------------------------
__global__ void layernorm_split_k(const float* __restrict__ xin,
                                  __nv_bfloat16* __restrict__ yhi,
                                  __nv_bfloat16* __restrict__ ylo,
                                  const float* __restrict__ w,
                                  const float* __restrict__ b) {
    const size_t row = blockIdx.x;
    const float* xr = xin + row * DM;
    const int d = threadIdx.x * 4;

    const float4 v = *(const float4*)(xr + d);
    float s  = v.x + v.y + v.z + v.w;
    float s2 = v.x*v.x + v.y*v.y + v.z*v.z + v.w*v.w;
    s  = block_reduce<false>(s);
    s2 = block_reduce<false>(s2);
    const float mean = s * (1.0f / DM);
    const float var  = s2 * (1.0f / DM) - mean * mean;
    const float rstd = rsqrtf(var + 1e-5f);

    const float4 ww = *(const float4*)(w + d);
    const float4 bb = *(const float4*)(b + d);
    float o0 = (v.x - mean) * rstd * ww.x + bb.x;
    float o1 = (v.y - mean) * rstd * ww.y + bb.y;
    float o2 = (v.z - mean) * rstd * ww.z + bb.z;
    float o3 = (v.w - mean) * rstd * ww.w + bb.w;
    __nv_bfloat16 h0,h1,h2,h3,l0,l1,l2,l3;
    split1(o0,h0,l0); split1(o1,h1,l1); split1(o2,h2,l2); split1(o3,h3,l3);
    __nv_bfloat162* ph = (__nv_bfloat162*)(yhi + row * DM + d);
    __nv_bfloat162* pl = (__nv_bfloat162*)(ylo + row * DM + d);
    ph[0] = __halves2bfloat162(h0,h1); ph[1] = __halves2bfloat162(h2,h3);
    pl[0] = __halves2bfloat162(l0,l1); pl[1] = __halves2bfloat162(l2,l3);
}

// ---------------------------------------------------------------------------
// Causal softmax, one pass (row cached in registers): fp32 -> bf16 hi/lo P.
// zero_upper: write zeros above diagonal (only needed in layer 0).
// ---------------------------------------------------------------------------
__global__ void softmax_split_k(const float* __restrict__ S,
                                __nv_bfloat16* __restrict__ Phi,
                                __nv_bfloat16* __restrict__ Plo,
                                int zero_upper) {
    const int  i = blockIdx.x;
    const long z = blockIdx.y;
    const size_t roff = ((size_t)z * TT + i) * TT;
    const float* row = S + roff;
    const int len = i + 1;

    float r[8];
    float m = -3.4e38f;
#pragma unroll
    for (int t = 0; t < 8; t++) {
        const int j = threadIdx.x + t * 256;
        r[t] = (j < len) ? row[j] : -3.4e38f;
        m = fmaxf(m, r[t]);
    }
    m = block_reduce<true>(m);

    float s = 0.0f;
#pragma unroll
    for (int t = 0; t < 8; t++) {
        const int j = threadIdx.x + t * 256;
        if (j < len) { r[t] = __expf(r[t] - m); s += r[t]; }
    }
    s = block_reduce<false>(s);
    const float inv = 1.0f / s;

#pragma unroll
    for (int t = 0; t < 8; t++) {
        const int j = threadIdx.x + t * 256;
        if (j < len) {
            __nv_bfloat16 h, l; split1(r[t] * inv, h, l);
            Phi[roff + j] = h; Plo[roff + j] = l;
        }
    }
    if (zero_upper) {
        const __nv_bfloat16 zz = __float2bfloat16(0.0f);
        for (int j = len + threadIdx.x; j < TT; j += blockDim.x) {
            Phi[roff + j] = zz; Plo[roff + j] = zz;
        }
    }
}

// ---------------------------------------------------------------------------
// mma.sync GEMM, bf16x3 split emulation of fp32.
//   C[m,n] = epi( scale * sum_k A[m,k] * B(n,k) ),  pre-split bf16 hi/lo planes.
//   BTR=true : B(n,k) = B[n*ldb+k]  (K-major weights / K matrix)
//   BTR=false: B(n,k) = B[k*ldb+n]  (N-major; V in P@V), BN=64
// BK=64, 3-stage cp.async ring, XOR-swizzled 128B smem rows (conflict-free
// LDSM), register double-buffered fragments, 8 warps (2m x 4n), warp tile
// 64 x (NT*8).  causal: 1 = skip tiles above diagonal, 2 = clip K to m0+BM.
//   OUT: 0 = fp32 C (+opt residual), 1 = split bf16 planes (+opt GELU)
// ---------------------------------------------------------------------------
template <int BM, int BN, bool BTR, int OUT, bool DOGELU>
__global__ __launch_bounds__(256, 1)
void tgemm_k(const __nv_bfloat16* __restrict__ Ahi, const __nv_bfloat16* __restrict__ Alo,
             long lda, long sAb, long sAh,
             const __nv_bfloat16* __restrict__ Bhi, const __nv_bfloat16* __restrict__ Blo,
             long ldb, long sBb, long sBh,
             float* __restrict__ C,
             __nv_bfloat16* __restrict__ Chi, __nv_bfloat16* __restrict__ Clo,
             long ldc, long sCb, long sCh,
             int M, int N, int K, int nheads,
             const float* __restrict__ bias,
             const float* __restrict__ resid,
             float scale, int causal) {
    constexpr int MT   = 4;                    // m16 tiles per warp (warp M = 64)
    constexpr int NT   = BN / 8 / 4;           // n8 tiles per warp (4 warps in N)
    constexpr int PLA  = 128 * 128;            // A plane bytes (128 rows x 128B)
    constexpr int BROW = BTR ? BN : 64;        // B smem rows
    constexpr int PLB  = BROW * 128;           // B plane bytes
    constexpr int SA   = 2 * PLA;              // 32768
    constexpr int STAGE = SA + 2 * PLB;
    static_assert(BM == 128, "BM=128 assumed by staging");

    extern __shared__ char smem[];
    const unsigned sb = (unsigned)__cvta_generic_to_shared(smem);

    const int z  = blockIdx.z;
    const int bb = z / nheads;
    const int hh = z - bb * nheads;
    Ahi += (size_t)bb * sAb + (size_t)hh * sAh;
    Alo += (size_t)bb * sAb + (size_t)hh * sAh;
    Bhi += (size_t)bb * sBb + (size_t)hh * sBh;
    Blo += (size_t)bb * sBb + (size_t)hh * sBh;
    const size_t coff = (size_t)bb * sCb + (size_t)hh * sCh;

    // tile raster: groups of 8 m-blocks for L2 reuse of B (gridDim.y % 8 == 0)
    const int gx  = gridDim.x;
    const int lin = blockIdx.y * gx + blockIdx.x;
    const int per = 8 * gx;
    const int m0 = ((lin / per) * 8 + (lin % 8)) * BM;
    const int n0 = ((lin % per) / 8) * BN;
    if (causal == 1 && n0 > m0 + BM - 1) return;
    const int Keff = (causal == 2) ? min(K, m0 + BM) : K;
    const int nIt  = Keff / 64;

    const int tid  = threadIdx.x;
    const int warp = tid >> 5;
    const int lane = tid & 31;
    const int wm   = warp & 1;
    const int wn   = warp >> 1;
    const int l8   = lane & 7;
    const int g    = lane >> 3;

    float acc[MT][NT][4];
#pragma unroll
    for (int i = 0; i < MT; i++)
#pragma unroll
        for (int j = 0; j < NT; j++)
#pragma unroll
            for (int q = 0; q < 4; q++) acc[i][j][q] = 0.0f;

    // ---------------- cp.async staging: one 64-wide K chunk ----------------
    auto issue = [&](int stg) {
        const unsigned so = sb + (unsigned)((stg % 3) * STAGE);
        const long kk = (long)stg * 64;
#pragma unroll
        for (int i = 0; i < 8; i++) {                 // A: 2 planes x 128r x 8c
            const int q  = tid + (i << 8);
            const int pl = q >> 10;
            const int r  = (q >> 3) & 127;
            const int c  = q & 7;
            const __nv_bfloat16* gp = (pl ? Alo : Ahi) + (size_t)(m0 + r) * lda + kk + c * 8;
            cp16(so + (unsigned)(pl * PLA + r * 128 + ((c ^ (r & 7)) << 4)), gp);
        }
        if (BTR) {
#pragma unroll
            for (int i = 0; i < 8; i++) {             // B: 2 planes x BN r x 8c
                const int q  = tid + (i << 8);
                const int pl = q >> 10;
                const int r  = (q >> 3) & 127;
                const int c  = q & 7;
                const __nv_bfloat16* gp = (pl ? Blo : Bhi) + (size_t)(n0 + r) * ldb + kk + c * 8;
                cp16(so + (unsigned)(SA + pl * PLB + r * 128 + ((c ^ (r & 7)) << 4)), gp);
            }
        } else {
#pragma unroll
            for (int i = 0; i < 4; i++) {             // B: 2 planes x 64 kr x 8c
                const int q  = tid + (i << 8);
                const int pl = q >> 9;
                const int r  = (q >> 3) & 63;
                const int c  = q & 7;
                const __nv_bfloat16* gp = (pl ? Blo : Bhi) + (size_t)(kk + r) * ldb + n0 + c * 8;
                cp16(so + (unsigned)(SA + pl * PLB + r * 128 + ((c ^ (r & 7)) << 4)), gp);
            }
        }
    };

    // ---------------- fragment loads (XOR-swizzled addresses) --------------
    const int aRow = (g & 1) * 8 + l8;   // row-within-tile for A ldmatrix lane
    const int aCh  = g >> 1;             // 16B-chunk half for A ldmatrix lane

    auto loadA = [&](unsigned sA0, int s, unsigned a[MT][2][4]) {
#pragma unroll
        for (int i = 0; i < MT; i++) {
            const int m  = wm * 64 + i * 16 + aRow;
            const int ch = 2 * s + aCh;
            const unsigned off = (unsigned)(m * 128 + ((ch ^ (m & 7)) << 4));
            ldsm4(a[i][0], sA0 + off);
            ldsm4(a[i][1], sA0 + PLA + off);
        }
    };
    auto loadB = [&](unsigned sB0, int s, unsigned b[NT][2][2]) {
        if (BTR) {
#pragma unroll
            for (int jp = 0; jp < NT / 2; jp++) {
                const int n  = wn * (NT * 8) + jp * 16 + (g >> 1) * 8 + l8;
                const int ch = 2 * s + (g & 1);
                const unsigned off = (unsigned)(n * 128 + ((ch ^ (n & 7)) << 4));
                unsigned t[4];
                ldsm4(t, sB0 + off);
                b[2*jp][0][0] = t[0]; b[2*jp][0][1] = t[1];
                b[2*jp+1][0][0] = t[2]; b[2*jp+1][0][1] = t[3];
                ldsm4(t, sB0 + PLB + off);
                b[2*jp][1][0] = t[0]; b[2*jp][1][1] = t[1];
                b[2*jp+1][1][0] = t[2]; b[2*jp+1][1][1] = t[3];
            }
        } else {
            // PV: NT == 2, one trans-x4 per plane covers both n-tiles
            const int klo = 16 * s + (g & 1) * 8 + l8;
            const int ch  = wn * 2 + (g >> 1);
            const unsigned off = (unsigned)(klo * 128 + ((ch ^ (klo & 7)) << 4));
            unsigned t[4];
            ldsm4t(t, sB0 + off);
            b[0][0][0] = t[0]; b[0][0][1] = t[1];
            b[1][0][0] = t[2]; b[1][0][1] = t[3];
            ldsm4t(t, sB0 + PLB + off);
            b[0][1][0] = t[0]; b[0][1][1] = t[1];
            b[1][1][0] = t[2]; b[1][1][1] = t[3];
        }
    };

    // ---------------- pipelined mainloop ----------------
    issue(0); cp_commit();
    if (nIt > 1) issue(1);
    cp_commit();

    for (int it = 0; it < nIt; it++) {
        if (it + 1 < nIt) cp_wait<1>(); else cp_wait<0>();
        __syncthreads();
        if (it + 2 < nIt) issue(it + 2);
        cp_commit();

        const unsigned sA0 = sb + (unsigned)((it % 3) * STAGE);
        const unsigned sB0 = sA0 + SA;

        unsigned ra[2][MT][2][4];
        unsigned rb[2][NT][2][2];
        loadA(sA0, 0, ra[0]);
        loadB(sB0, 0, rb[0]);
#pragma unroll
        for (int s = 0; s < 4; s++) {
            const int cur = s & 1;
            if (s < 3) {
                loadA(sA0, s + 1, ra[cur ^ 1]);
                loadB(sB0, s + 1, rb[cur ^ 1]);
            }
#pragma unroll
            for (int i = 0; i < MT; i++)
#pragma unroll
                for (int j = 0; j < NT; j++) {
                    mma16816(acc[i][j], ra[cur][i][0], rb[cur][j][0]);   // hi*hi
                    mma16816(acc[i][j], ra[cur][i][0], rb[cur][j][1]);   // hi*lo
                    mma16816(acc[i][j], ra[cur][i][1], rb[cur][j][0]);   // lo*hi
                }
        }
        __syncthreads();   // all warps done with this stage before it is refilled
    }
    cp_wait<0>();

    // ---------------- epilogue ----------------
#pragma unroll
    for (int i = 0; i < MT; i++) {
        const int row = m0 + wm * 64 + i * 16 + (lane >> 2);
#pragma unroll
        for (int j = 0; j < NT; j++) {
            const int col = n0 + wn * (NT * 8) + j * 8 + ((lane & 3) << 1);
            float b0 = 0.f, b1 = 0.f;
            if (bias) { b0 = bias[col]; b1 = bias[col + 1]; }
#pragma unroll
            for (int hlf = 0; hlf < 2; hlf++) {
                const int r = row + hlf * 8;
                float v0 = acc[i][j][hlf * 2 + 0] * scale + b0;
                float v1 = acc[i][j][hlf * 2 + 1] * scale + b1;
                if (DOGELU) { v0 = gelu_exact(v0); v1 = gelu_exact(v1); }
                const size_t idx = coff + (size_t)r * ldc + col;
                if (OUT == 0) {
                    if (resid) {
                        const float2 rr = *(const float2*)(resid + idx);
                        v0 += rr.x; v1 += rr.y;
                    }
                    float2 o; o.x = v0; o.y = v1;
                    *(float2*)(C + idx) = o;
                } else {
                    __nv_bfloat16 h0, h1, l0, l1;
                    split1(v0, h0, l0); split1(v1, h1, l1);
                    *(__nv_bfloat162*)(Chi + idx) = __halves2bfloat162(h0, h1);
                    *(__nv_bfloat162*)(Clo + idx) = __halves2bfloat162(l0, l1);
                }
            }
        }
    }
}

// ---------------------------------------------------------------------------
// Host orchestration
// ---------------------------------------------------------------------------
extern "C" void kernel_launch(void* const* d_in, const int* in_sizes, int n_in,
                              void* d_out, int out_size) {
    (void)in_sizes; (void)n_in; (void)out_size;
    const int*   ids   = (const int*)  d_in[0];
    const float* ctx   = (const float*)d_in[1];
    const float* tok   = (const float*)d_in[2];
    const float* pos   = (const float*)d_in[3];
    const float* qkvw  = (const float*)d_in[4];
    const float* qkvb  = (const float*)d_in[5];
    const float* projw = (const float*)d_in[6];
    const float* projb = (const float*)d_in[7];
    const float* ln1w  = (const float*)d_in[8];
    const float* ln1b  = (const float*)d_in[9];
    const float* ln2w  = (const float*)d_in[10];
    const float* ln2b  = (const float*)d_in[11];
    const float* f1w   = (const float*)d_in[12];
    const float* f1b   = (const float*)d_in[13];
    const float* f2w   = (const float*)d_in[14];
    const float* f2b   = (const float*)d_in[15];
    const float* lnfw  = (const float*)d_in[16];
    const float* lnfb  = (const float*)d_in[17];
    float* out = (float*)d_out;

    float *x, *sc;
    __nv_bfloat16 *hhi,*hlo,*qhi,*qlo,*ahi,*alo,*mhi,*mlo,*phi,*plo,*whi,*wlo;
    cudaGetSymbolAddress((void**)&x,   g_x);
    cudaGetSymbolAddress((void**)&sc,  g_sc);
    cudaGetSymbolAddress((void**)&hhi, g_h_hi);   cudaGetSymbolAddress((void**)&hlo, g_h_lo);
    cudaGetSymbolAddress((void**)&qhi, g_qkv_hi); cudaGetSymbolAddress((void**)&qlo, g_qkv_lo);
    cudaGetSymbolAddress((void**)&ahi, g_at_hi);  cudaGetSymbolAddress((void**)&alo, g_at_lo);
    cudaGetSymbolAddress((void**)&mhi, g_mid_hi); cudaGetSymbolAddress((void**)&mlo, g_mid_lo);
    cudaGetSymbolAddress((void**)&phi, g_p_hi);   cudaGetSymbolAddress((void**)&plo, g_p_lo);
    cudaGetSymbolAddress((void**)&whi, g_w_hi);   cudaGetSymbolAddress((void**)&wlo, g_w_lo);

    auto kF32  = tgemm_k<128,128,true ,0,false>;   // fp32 out (+resid)
    auto kSPL  = tgemm_k<128,128,true ,1,false>;   // split planes out
    auto kSPLG = tgemm_k<128,128,true ,1,true >;   // split planes out + GELU
    auto kPV   = tgemm_k<128, 64,false,1,false>;   // P @ V (N-major B)

    const int SM_NT = 3 * (2*128*128 + 2*128*128);   // 196608
    const int SM_PV = 3 * (2*128*128 + 2*64*128);    // 147456
    cudaFuncSetAttribute(kF32,  cudaFuncAttributeMaxDynamicSharedMemorySize, SM_NT);
    cudaFuncSetAttribute(kSPL,  cudaFuncAttributeMaxDynamicSharedMemorySize, SM_NT);
    cudaFuncSetAttribute(kSPLG, cudaFuncAttributeMaxDynamicSharedMemorySize, SM_NT);
    cudaFuncSetAttribute(kPV,   cudaFuncAttributeMaxDynamicSharedMemorySize, SM_PV);

    // ---- split all weights into bf16 hi/lo planes ----
    split_k<<<2048, 256>>>(qkvw,  whi + QW_OFF, wlo + QW_OFF, (long)(QW_SZ / 4));
    split_k<<<2048, 256>>>(projw, whi + PW_OFF, wlo + PW_OFF, (long)(PW_SZ / 4));
    split_k<<<2048, 256>>>(f1w,   whi + F1_OFF, wlo + F1_OFF, (long)(F1_SZ / 4));
    split_k<<<2048, 256>>>(f2w,   whi + F2_OFF, wlo + F2_OFF, (long)(F2_SZ / 4));
    split_k<<<2048, 256>>>(tok,   whi + TK_OFF, wlo + TK_OFF, (long)(TK_SZ / 4));

    const float attn_scale = 0.125f;   // 1/sqrt(64)

    embed_k<<<BTOK, 256>>>(ids, tok, pos, ctx, x);

    for (int l = 0; l < LAYERS; l++) {
        layernorm_split_k<<<BTOK, 256>>>(x, hhi, hlo,
                                         ln1w + (size_t)l*DM, ln1b + (size_t)l*DM);

        // qkv = h @ qkv_w^T + qkv_b  -> split planes
        kSPL<<<dim3(24, 32, 1), 256, SM_NT>>>(
            hhi, hlo, DM, 0, 0,
            whi + QW_OFF + (size_t)l*3*DM*DM, wlo + QW_OFF + (size_t)l*3*DM*DM, DM, 0, 0,
            nullptr, qhi, qlo, 3*DM, 0, 0,
            BTOK, 3*DM, DM, 1,
            qkvb + (size_t)l*3*DM, nullptr, 1.0f, 0);

        // scores = scale * Q @ K^T (fp32, skip upper-triangle tiles; K=64 -> 1 iter)
        kF32<<<dim3(16, 16, BBATCH*NH), 256, SM_NT>>>(
            qhi,      qlo,      3*DM, (long)TT*3*DM, HDIM,
            qhi + DM, qlo + DM, 3*DM, (long)TT*3*DM, HDIM,
            sc, nullptr, nullptr, TT, (long)NH*TT*TT, (long)TT*TT,
            TT, TT, HDIM, NH,
            nullptr, nullptr, attn_scale, 1);

        softmax_split_k<<<dim3(TT, BBATCH*NH), 256>>>(sc, phi, plo, l == 0 ? 1 : 0);

        // attn = P @ V  (K clipped to m0+128) -> split planes
        kPV<<<dim3(1, 16, BBATCH*NH), 256, SM_PV>>>(
            phi, plo, TT, (long)NH*TT*TT, (long)TT*TT,
            qhi + 2*DM, qlo + 2*DM, 3*DM, (long)TT*3*DM, HDIM,
            nullptr, ahi, alo, DM, (long)TT*DM, HDIM,
            TT, HDIM, TT, NH,
            nullptr, nullptr, 1.0f, 2);

        // x += attn @ proj_w^T + proj_b  (fp32 + residual)
        kF32<<<dim3(8, 32, 1), 256, SM_NT>>>(
            ahi, alo, DM, 0, 0,
            whi + PW_OFF + (size_t)l*DM*DM, wlo + PW_OFF + (size_t)l*DM*DM, DM, 0, 0,
            x, nullptr, nullptr, DM, 0, 0,
            BTOK, DM, DM, 1,
            projb + (size_t)l*DM, x, 1.0f, 0);

        layernorm_split_k<<<BTOK, 256>>>(x, hhi, hlo,
                                         ln2w + (size_t)l*DM, ln2b + (size_t)l*DM);

        // mid = gelu(h @ f1_w^T + f1_b) -> split planes
        kSPLG<<<dim3(32, 32, 1), 256, SM_NT>>>(
            hhi, hlo, DM, 0, 0,
            whi + F1_OFF + (size_t)l*4*DM*DM, wlo + F1_OFF + (size_t)l*4*DM*DM, DM, 0, 0,
            nullptr, mhi, mlo, 4*DM, 0, 0,
            BTOK, 4*DM, DM, 1,
            f1b + (size_t)l*4*DM, nullptr, 1.0f, 0);

        // x += mid @ f2_w^T + f2_b  (fp32 + residual)
        kF32<<<dim3(8, 32, 1), 256, SM_NT>>>(
            mhi, mlo, 4*DM, 0, 0,
            whi + F2_OFF + (size_t)l*DM*4*DM, wlo + F2_OFF + (size_t)l*DM*4*DM, 4*DM, 0, 0,
            x, nullptr, nullptr, DM, 0, 0,
            BTOK, DM, 4*DM, 1,
            f2b + (size_t)l*DM, x, 1.0f, 0);
    }

    layernorm_split_k<<<BTOK, 256>>>(x, hhi, hlo, lnfw, lnfb);

    // logits = h @ tok_emb^T (fp32)
    kF32<<<dim3(250, 32, 1), 256, SM_NT>>>(
        hhi, hlo, DM, 0, 0,
        whi + TK_OFF, wlo + TK_OFF, DM, 0, 0,
        out, nullptr, nullptr, VO, 0, 0,
        BTOK, VO, DM, 1,
        nullptr, nullptr, 1.0f, 0);
}

// round 16
// speedup vs baseline: 3.1479x; 1.1662x over previous
#include <cuda_runtime.h>
#include <cuda_bf16.h>
#include <math.h>

// ---------------------------------------------------------------------------
// Problem constants
// ---------------------------------------------------------------------------
#define LAYERS 4
#define NH     16
#define DM     1024
#define VO     32000
#define TT     2048
#define BBATCH 2
#define HDIM   64
#define BTOK   (BBATCH*TT)   // 4096

// weight-plane offsets (elements)
#define QW_SZ  ((size_t)LAYERS*3*DM*DM)
#define PW_SZ  ((size_t)LAYERS*DM*DM)
#define F1_SZ  ((size_t)LAYERS*4*DM*DM)
#define F2_SZ  ((size_t)LAYERS*4*DM*DM)
#define TK_SZ  ((size_t)VO*DM)
#define QW_OFF ((size_t)0)
#define PW_OFF (QW_OFF+QW_SZ)
#define F1_OFF (PW_OFF+PW_SZ)
#define F2_OFF (F1_OFF+F1_SZ)
#define TK_OFF (F2_OFF+F2_SZ)
#define W_TOTAL (TK_OFF+TK_SZ)

// ---------------------------------------------------------------------------
// Scratch (static __device__ arrays: the sanctioned no-alloc path)
// ---------------------------------------------------------------------------
__device__ float g_x [(size_t)BTOK * DM];

__device__ __nv_bfloat16 g_h_hi  [(size_t)BTOK * DM];
__device__ __nv_bfloat16 g_h_lo  [(size_t)BTOK * DM];
__device__ __nv_bfloat16 g_qkv_hi[(size_t)BTOK * 3 * DM];
__device__ __nv_bfloat16 g_qkv_lo[(size_t)BTOK * 3 * DM];
__device__ __nv_bfloat16 g_at_hi [(size_t)BTOK * DM];
__device__ __nv_bfloat16 g_at_lo [(size_t)BTOK * DM];
__device__ __nv_bfloat16 g_mid_hi[(size_t)BTOK * 4 * DM];
__device__ __nv_bfloat16 g_mid_lo[(size_t)BTOK * 4 * DM];
__device__ __nv_bfloat16 g_w_hi  [W_TOTAL];
__device__ __nv_bfloat16 g_w_lo  [W_TOTAL];

// ---------------------------------------------------------------------------
// Small helpers
// ---------------------------------------------------------------------------
__device__ __forceinline__ float gelu_exact(float x) {
    return 0.5f * x * (1.0f + erff(x * 0.70710678118654752440f));
}
__device__ __forceinline__ void split1(float v, __nv_bfloat16& h, __nv_bfloat16& l) {
    h = __float2bfloat16(v);
    l = __float2bfloat16(v - __bfloat162float(h));
}
// split fp32 pair into packed bf16x2 hi & lo words
__device__ __forceinline__ void split_pack2(float x, float y, unsigned& h, unsigned& l) {
    __nv_bfloat16 xh, xl, yh, yl;
    split1(x, xh, xl); split1(y, yh, yl);
    __nv_bfloat162 hh = __halves2bfloat162(xh, yh);
    __nv_bfloat162 ll = __halves2bfloat162(xl, yl);
    h = *reinterpret_cast<unsigned*>(&hh);
    l = *reinterpret_cast<unsigned*>(&ll);
}

template <bool DOMAX>
__device__ __forceinline__ float block_reduce(float v) {
    __shared__ float sh[33];
    const int lane = threadIdx.x & 31;
    const int wid  = threadIdx.x >> 5;
#pragma unroll
    for (int o = 16; o; o >>= 1) {
        float t = __shfl_xor_sync(0xffffffffu, v, o);
        v = DOMAX ? fmaxf(v, t) : (v + t);
    }
    if (lane == 0) sh[wid] = v;
    __syncthreads();
    const int nw = blockDim.x >> 5;
    if (wid == 0) {
        float t = (lane < nw) ? sh[lane] : (DOMAX ? -3.4e38f : 0.0f);
#pragma unroll
        for (int o = 16; o; o >>= 1) {
            float u = __shfl_xor_sync(0xffffffffu, t, o);
            t = DOMAX ? fmaxf(t, u) : (t + u);
        }
        if (lane == 0) sh[32] = t;
    }
    __syncthreads();
    float r = sh[32];
    __syncthreads();
    return r;
}

__device__ __forceinline__ void mma16816(float* c, const unsigned* a, const unsigned* b) {
    asm volatile(
        "mma.sync.aligned.m16n8k16.row.col.f32.bf16.bf16.f32 "
        "{%0,%1,%2,%3}, {%4,%5,%6,%7}, {%8,%9}, {%0,%1,%2,%3};\n"
        : "+f"(c[0]), "+f"(c[1]), "+f"(c[2]), "+f"(c[3])
        : "r"(a[0]), "r"(a[1]), "r"(a[2]), "r"(a[3]), "r"(b[0]), "r"(b[1]));
}
__device__ __forceinline__ void ldsm4(unsigned* r, unsigned a) {
    asm volatile("ldmatrix.sync.aligned.m8n8.x4.shared.b16 {%0,%1,%2,%3}, [%4];"
                 : "=r"(r[0]), "=r"(r[1]), "=r"(r[2]), "=r"(r[3]) : "r"(a));
}
__device__ __forceinline__ void ldsm4t(unsigned* r, unsigned a) {
    asm volatile("ldmatrix.sync.aligned.m8n8.x4.trans.shared.b16 {%0,%1,%2,%3}, [%4];"
                 : "=r"(r[0]), "=r"(r[1]), "=r"(r[2]), "=r"(r[3]) : "r"(a));
}
__device__ __forceinline__ void cp16(unsigned saddr, const void* g) {
    asm volatile("cp.async.cg.shared.global [%0], [%1], 16;" :: "r"(saddr), "l"(g));
}
__device__ __forceinline__ void cp_commit() { asm volatile("cp.async.commit_group;"); }
template <int N>
__device__ __forceinline__ void cp_wait() { asm volatile("cp.async.wait_group %0;" :: "n"(N)); }

// ---------------------------------------------------------------------------
// fp32 -> bf16 hi/lo split (weights)
// ---------------------------------------------------------------------------
__global__ void split_k(const float* __restrict__ s,
                        __nv_bfloat16* __restrict__ hi,
                        __nv_bfloat16* __restrict__ lo, long n4) {
    long i = (long)blockIdx.x * blockDim.x + threadIdx.x;
    const long stride = (long)gridDim.x * blockDim.x;
    for (; i < n4; i += stride) {
        float4 v = ((const float4*)s)[i];
        unsigned h0, l0, h1, l1;
        split_pack2(v.x, v.y, h0, l0);
        split_pack2(v.z, v.w, h1, l1);
        ((unsigned*)hi)[2*i+0] = h0;
        ((unsigned*)hi)[2*i+1] = h1;
        ((unsigned*)lo)[2*i+0] = l0;
        ((unsigned*)lo)[2*i+1] = l1;
    }
}

// ---------------------------------------------------------------------------
// Embedding (fp32 residual)
// ---------------------------------------------------------------------------
__global__ void embed_k(const int* __restrict__ ids,
                        const float* __restrict__ tok,
                        const float* __restrict__ pos,
                        const float* __restrict__ ctx,
                        float* __restrict__ x) {
    const int bt = blockIdx.x;
    const int b  = bt / TT;
    const int t  = bt - b * TT;
    const int id = ids[bt];
    const int d  = threadIdx.x * 4;
    const float4 a = *(const float4*)(tok + (size_t)id * DM + d);
    const float4 p = *(const float4*)(pos + (size_t)t  * DM + d);
    const float4 c = *(const float4*)(ctx + (size_t)b  * DM + d);
    float4 r;
    r.x = a.x + p.x + c.x; r.y = a.y + p.y + c.y;
    r.z = a.z + p.z + c.z; r.w = a.w + p.w + c.w;
    *(float4*)(x + (size_t)bt * DM + d) = r;
}

// ---------------------------------------------------------------------------
// LayerNorm: fp32 in -> bf16 hi/lo planes out
// ---------------------------------------------------------------------------
__global__ void layernorm_split_k(const float* __restrict__ xin,
                                  __nv_bfloat16* __restrict__ yhi,
                                  __nv_bfloat16* __restrict__ ylo,
                                  const float* __restrict__ w,
                                  const float* __restrict__ b) {
    const size_t row = blockIdx.x;
    const float* xr = xin + row * DM;
    const int d = threadIdx.x * 4;

    const float4 v = *(const float4*)(xr + d);
    float s  = v.x + v.y + v.z + v.w;
    float s2 = v.x*v.x + v.y*v.y + v.z*v.z + v.w*v.w;
    s  = block_reduce<false>(s);
    s2 = block_reduce<false>(s2);
    const float mean = s * (1.0f / DM);
    const float var  = s2 * (1.0f / DM) - mean * mean;
    const float rstd = rsqrtf(var + 1e-5f);

    const float4 ww = *(const float4*)(w + d);
    const float4 bb = *(const float4*)(b + d);
    float o0 = (v.x - mean) * rstd * ww.x + bb.x;
    float o1 = (v.y - mean) * rstd * ww.y + bb.y;
    float o2 = (v.z - mean) * rstd * ww.z + bb.z;
    float o3 = (v.w - mean) * rstd * ww.w + bb.w;
    unsigned h0, l0, h1, l1;
    split_pack2(o0, o1, h0, l0);
    split_pack2(o2, o3, h1, l1);
    unsigned* ph = (unsigned*)(yhi + row * DM + d);
    unsigned* pl = (unsigned*)(ylo + row * DM + d);
    ph[0] = h0; ph[1] = h1;
    pl[0] = l0; pl[1] = l1;
}

// ---------------------------------------------------------------------------
// Flash attention (causal), bf16x3 precision, online fp32 softmax.
// grid = (T/128, B*NH); 256 threads = 8 warps, warp w owns Q rows
// m0 + 16w .. +15.  K/V blocks of 128 tokens streamed through a 3-stage
// cp.async ring (Khi|Klo|Vhi|Vlo, 16KB each, XOR-swizzled 128B rows).
// S fragments stay in registers; P packs directly into mma A-fragments.
// ---------------------------------------------------------------------------
__global__ __launch_bounds__(256, 1)
void fattn_k(const __nv_bfloat16* __restrict__ QKVhi,
             const __nv_bfloat16* __restrict__ QKVlo,
             __nv_bfloat16* __restrict__ Ohi,
             __nv_bfloat16* __restrict__ Olo,
             float scale) {
    constexpr int PL  = 128 * 128;   // one plane: 128 rows x 128B
    constexpr int STG = 4 * PL;      // 64 KB per stage

    extern __shared__ char smem[];
    const unsigned sb = (unsigned)__cvta_generic_to_shared(smem);

    const int z  = blockIdx.y;
    const int bb = z / NH;
    const int hh = z - bb * NH;
    const int qb = (int)gridDim.x - 1 - (int)blockIdx.x;   // heavy tiles first
    const int m0 = qb * 128;

    const int tid  = threadIdx.x;
    const int warp = tid >> 5;
    const int lane = tid & 31;
    const int g    = lane >> 3;
    const int l8   = lane & 7;
    const int qr   = lane >> 2;          // row-in-tile (0..7)
    const int qc   = (lane & 3) * 2;     // col pair base

    const size_t rowbase = (size_t)bb * TT;
    const size_t hoff    = (size_t)hh * HDIM;

    // ---- Q fragments: direct LDG from split planes (A-frag layout) ----
    unsigned qf[2][4][4];   // [plane][k16-chunk][reg]
    {
        const int r0 = m0 + warp * 16 + qr;
        const size_t a0 = (rowbase + r0) * (size_t)(3 * DM) + hoff;
        const size_t a1 = a0 + (size_t)8 * (3 * DM);
#pragma unroll
        for (int p = 0; p < 2; p++) {
            const __nv_bfloat16* src = p ? QKVlo : QKVhi;
#pragma unroll
            for (int c = 0; c < 4; c++) {
                const int k = c * 16 + qc;
                qf[p][c][0] = *(const unsigned*)(src + a0 + k);
                qf[p][c][1] = *(const unsigned*)(src + a1 + k);
                qf[p][c][2] = *(const unsigned*)(src + a0 + k + 8);
                qf[p][c][3] = *(const unsigned*)(src + a1 + k + 8);
            }
        }
    }

    float oacc[8][4];
#pragma unroll
    for (int t = 0; t < 8; t++)
#pragma unroll
        for (int e = 0; e < 4; e++) oacc[t][e] = 0.0f;
    float m0r = -1e30f, m1r = -1e30f;    // running max (rows r0 / r1)
    float l0r = 0.0f,   l1r = 0.0f;      // running sum

    // ---- K/V block staging ----
    auto issueKV = [&](int kb) {
        const unsigned so = sb + (unsigned)((kb % 3) * STG);
        const size_t tok0 = rowbase + (size_t)kb * 128;
#pragma unroll
        for (int i = 0; i < 8; i++) {     // K planes
            const int q  = tid + (i << 8);
            const int pl = q >> 10;
            const int r  = (q >> 3) & 127;
            const int c  = q & 7;
            const __nv_bfloat16* gp =
                (pl ? QKVlo : QKVhi) + (tok0 + r) * (size_t)(3 * DM) + DM + hoff + c * 8;
            cp16(so + (unsigned)(pl * PL + r * 128 + ((c ^ (r & 7)) << 4)), gp);
        }
#pragma unroll
        for (int i = 0; i < 8; i++) {     // V planes
            const int q  = tid + (i << 8);
            const int pl = q >> 10;
            const int r  = (q >> 3) & 127;
            const int c  = q & 7;
            const __nv_bfloat16* gp =
                (pl ? QKVlo : QKVhi) + (tok0 + r) * (size_t)(3 * DM) + 2 * DM + hoff + c * 8;
            cp16(so + (unsigned)(2 * PL + pl * PL + r * 128 + ((c ^ (r & 7)) << 4)), gp);
        }
    };

    issueKV(0); cp_commit();
    if (qb >= 1) issueKV(1);
    cp_commit();

    const int gr0 = m0 + warp * 16 + qr;
    const int gr1 = gr0 + 8;

    for (int kb = 0; kb <= qb; kb++) {
        if (kb < qb) cp_wait<1>(); else cp_wait<0>();
        __syncthreads();                       // all warps past previous compute
        if (kb + 2 <= qb) issueKV(kb + 2);
        cp_commit();

        const unsigned sK = sb + (unsigned)((kb % 3) * STG);
        const unsigned sV = sK + 2 * PL;

        // ---- S = scale * Q @ K^T (16 n-tiles of 8 cols) ----
        float sacc[16][4];
#pragma unroll
        for (int t = 0; t < 16; t++)
#pragma unroll
            for (int e = 0; e < 4; e++) sacc[t][e] = 0.0f;

#pragma unroll
        for (int s = 0; s < 4; s++) {
#pragma unroll
            for (int jp = 0; jp < 8; jp++) {
                const int n  = 16 * jp + (g >> 1) * 8 + l8;
                const int ch = 2 * s + (g & 1);
                const unsigned off = (unsigned)(n * 128 + ((ch ^ (n & 7)) << 4));
                unsigned bh[4], bl[4];
                ldsm4(bh, sK + off);
                ldsm4(bl, sK + PL + off);
                mma16816(sacc[2*jp],   qf[0][s], bh);       // hi*hi
                mma16816(sacc[2*jp],   qf[0][s], bl);       // hi*lo
                mma16816(sacc[2*jp],   qf[1][s], bh);       // lo*hi
                mma16816(sacc[2*jp+1], qf[0][s], bh + 2);
                mma16816(sacc[2*jp+1], qf[0][s], bl + 2);
                mma16816(sacc[2*jp+1], qf[1][s], bh + 2);
            }
        }

        // ---- scale, causal mask, online softmax ----
        float mx0 = -1e30f, mx1 = -1e30f;
        const bool diag = (kb == qb);
#pragma unroll
        for (int t = 0; t < 16; t++) {
            sacc[t][0] *= scale; sacc[t][1] *= scale;
            sacc[t][2] *= scale; sacc[t][3] *= scale;
            if (diag) {
                const int cb = kb * 128 + 8 * t + qc;
                if (cb     > gr0) sacc[t][0] = -1e30f;
                if (cb + 1 > gr0) sacc[t][1] = -1e30f;
                if (cb     > gr1) sacc[t][2] = -1e30f;
                if (cb + 1 > gr1) sacc[t][3] = -1e30f;
            }
            mx0 = fmaxf(mx0, fmaxf(sacc[t][0], sacc[t][1]));
            mx1 = fmaxf(mx1, fmaxf(sacc[t][2], sacc[t][3]));
        }
        mx0 = fmaxf(mx0, __shfl_xor_sync(0xffffffffu, mx0, 1));
        mx0 = fmaxf(mx0, __shfl_xor_sync(0xffffffffu, mx0, 2));
        mx1 = fmaxf(mx1, __shfl_xor_sync(0xffffffffu, mx1, 1));
        mx1 = fmaxf(mx1, __shfl_xor_sync(0xffffffffu, mx1, 2));

        const float mn0 = fmaxf(m0r, mx0);
        const float mn1 = fmaxf(m1r, mx1);
        const float sc0 = __expf(m0r - mn0);
        const float sc1 = __expf(m1r - mn1);
        m0r = mn0; m1r = mn1;

#pragma unroll
        for (int t = 0; t < 8; t++) {
            oacc[t][0] *= sc0; oacc[t][1] *= sc0;
            oacc[t][2] *= sc1; oacc[t][3] *= sc1;
        }

        float sum0 = 0.0f, sum1 = 0.0f;
#pragma unroll
        for (int t = 0; t < 16; t++) {
            sacc[t][0] = __expf(sacc[t][0] - mn0);
            sacc[t][1] = __expf(sacc[t][1] - mn0);
            sacc[t][2] = __expf(sacc[t][2] - mn1);
            sacc[t][3] = __expf(sacc[t][3] - mn1);
            sum0 += sacc[t][0] + sacc[t][1];
            sum1 += sacc[t][2] + sacc[t][3];
        }
        sum0 += __shfl_xor_sync(0xffffffffu, sum0, 1);
        sum0 += __shfl_xor_sync(0xffffffffu, sum0, 2);
        sum1 += __shfl_xor_sync(0xffffffffu, sum1, 1);
        sum1 += __shfl_xor_sync(0xffffffffu, sum1, 2);
        l0r = l0r * sc0 + sum0;
        l1r = l1r * sc1 + sum1;

        // ---- O += P @ V  (P packs straight into A fragments) ----
#pragma unroll
        for (int c = 0; c < 8; c++) {
            unsigned ph[4], pl_[4];
            split_pack2(sacc[2*c][0],   sacc[2*c][1],   ph[0], pl_[0]);
            split_pack2(sacc[2*c][2],   sacc[2*c][3],   ph[1], pl_[1]);
            split_pack2(sacc[2*c+1][0], sacc[2*c+1][1], ph[2], pl_[2]);
            split_pack2(sacc[2*c+1][2], sacc[2*c+1][3], ph[3], pl_[3]);
            const int klo = 16 * c + (g & 1) * 8 + l8;
#pragma unroll
            for (int jp = 0; jp < 4; jp++) {
                const int ch = 2 * jp + (g >> 1);
                const unsigned off = (unsigned)(klo * 128 + ((ch ^ (klo & 7)) << 4));
                unsigned vh[4], vl[4];
                ldsm4t(vh, sV + off);
                ldsm4t(vl, sV + PL + off);
                mma16816(oacc[2*jp],   ph,  vh);        // hi*hi
                mma16816(oacc[2*jp],   ph,  vl);        // hi*lo
                mma16816(oacc[2*jp],   pl_, vh);        // lo*hi
                mma16816(oacc[2*jp+1], ph,  vh + 2);
                mma16816(oacc[2*jp+1], ph,  vl + 2);
                mma16816(oacc[2*jp+1], pl_, vh + 2);
            }
        }
    }

    // ---- epilogue: O /= l, split, store ----
    const float inv0 = 1.0f / l0r;
    const float inv1 = 1.0f / l1r;
    const size_t o0 = (rowbase + gr0) * (size_t)DM + hoff;
    const size_t o1 = (rowbase + gr1) * (size_t)DM + hoff;
#pragma unroll
    for (int t = 0; t < 8; t++) {
        const int n = 8 * t + qc;
        unsigned h, l;
        split_pack2(oacc[t][0] * inv0, oacc[t][1] * inv0, h, l);
        *(unsigned*)(Ohi + o0 + n) = h;
        *(unsigned*)(Olo + o0 + n) = l;
        split_pack2(oacc[t][2] * inv1, oacc[t][3] * inv1, h, l);
        *(unsigned*)(Ohi + o1 + n) = h;
        *(unsigned*)(Olo + o1 + n) = l;
    }
}

// ---------------------------------------------------------------------------
// mma.sync GEMM, bf16x3 split emulation of fp32 (NT weights path).
//   C[m,n] = epi( scale * sum_k A[m,k] * B[n,k] ),  pre-split bf16 planes.
// BK=64, 3-stage cp.async ring, XOR-swizzled 128B rows, register
// double-buffered fragments, 8 warps (2m x 4n), warp tile 64x32.
//   OUT: 0 = fp32 C (+opt residual), 1 = split bf16 planes (+opt GELU)
// ---------------------------------------------------------------------------
template <int BM, int BN, int OUT, bool DOGELU>
__global__ __launch_bounds__(256, 1)
void tgemm_k(const __nv_bfloat16* __restrict__ Ahi, const __nv_bfloat16* __restrict__ Alo,
             long lda,
             const __nv_bfloat16* __restrict__ Bhi, const __nv_bfloat16* __restrict__ Blo,
             long ldb,
             float* __restrict__ C,
             __nv_bfloat16* __restrict__ Chi, __nv_bfloat16* __restrict__ Clo,
             long ldc,
             int K,
             const float* __restrict__ bias,
             const float* __restrict__ resid,
             float scale) {
    constexpr int MT   = 4;
    constexpr int NT   = BN / 8 / 4;
    constexpr int PLA  = 128 * 128;
    constexpr int PLB  = BN * 128;
    constexpr int SA   = 2 * PLA;
    constexpr int STAGE = SA + 2 * PLB;
    static_assert(BM == 128, "BM=128 assumed by staging");

    extern __shared__ char smem[];
    const unsigned sb = (unsigned)__cvta_generic_to_shared(smem);

    // tile raster: groups of 8 m-blocks for L2 reuse of B (gridDim.y % 8 == 0)
    const int gx  = gridDim.x;
    const int lin = blockIdx.y * gx + blockIdx.x;
    const int per = 8 * gx;
    const int m0 = ((lin / per) * 8 + (lin % 8)) * BM;
    const int n0 = ((lin % per) / 8) * BN;
    const int nIt = K / 64;

    const int tid  = threadIdx.x;
    const int warp = tid >> 5;
    const int lane = tid & 31;
    const int wm   = warp & 1;
    const int wn   = warp >> 1;
    const int l8   = lane & 7;
    const int g    = lane >> 3;

    float acc[MT][NT][4];
#pragma unroll
    for (int i = 0; i < MT; i++)
#pragma unroll
        for (int j = 0; j < NT; j++)
#pragma unroll
            for (int q = 0; q < 4; q++) acc[i][j][q] = 0.0f;

    auto issue = [&](int stg) {
        const unsigned so = sb + (unsigned)((stg % 3) * STAGE);
        const long kk = (long)stg * 64;
#pragma unroll
        for (int i = 0; i < 8; i++) {
            const int q  = tid + (i << 8);
            const int pl = q >> 10;
            const int r  = (q >> 3) & 127;
            const int c  = q & 7;
            const __nv_bfloat16* gp = (pl ? Alo : Ahi) + (size_t)(m0 + r) * lda + kk + c * 8;
            cp16(so + (unsigned)(pl * PLA + r * 128 + ((c ^ (r & 7)) << 4)), gp);
        }
#pragma unroll
        for (int i = 0; i < 8; i++) {
            const int q  = tid + (i << 8);
            const int pl = q >> 10;
            const int r  = (q >> 3) & 127;
            const int c  = q & 7;
            const __nv_bfloat16* gp = (pl ? Blo : Bhi) + (size_t)(n0 + r) * ldb + kk + c * 8;
            cp16(so + (unsigned)(SA + pl * PLB + r * 128 + ((c ^ (r & 7)) << 4)), gp);
        }
    };

    const int aRow = (g & 1) * 8 + l8;
    const int aCh  = g >> 1;

    auto loadA = [&](unsigned sA0, int s, unsigned a[MT][2][4]) {
#pragma unroll
        for (int i = 0; i < MT; i++) {
            const int m  = wm * 64 + i * 16 + aRow;
            const int ch = 2 * s + aCh;
            const unsigned off = (unsigned)(m * 128 + ((ch ^ (m & 7)) << 4));
            ldsm4(a[i][0], sA0 + off);
            ldsm4(a[i][1], sA0 + PLA + off);
        }
    };
    auto loadB = [&](unsigned sB0, int s, unsigned b[NT][2][2]) {
#pragma unroll
        for (int jp = 0; jp < NT / 2; jp++) {
            const int n  = wn * (NT * 8) + jp * 16 + (g >> 1) * 8 + l8;
            const int ch = 2 * s + (g & 1);
            const unsigned off = (unsigned)(n * 128 + ((ch ^ (n & 7)) << 4));
            unsigned t[4];
            ldsm4(t, sB0 + off);
            b[2*jp][0][0] = t[0]; b[2*jp][0][1] = t[1];
            b[2*jp+1][0][0] = t[2]; b[2*jp+1][0][1] = t[3];
            ldsm4(t, sB0 + PLB + off);
            b[2*jp][1][0] = t[0]; b[2*jp][1][1] = t[1];
            b[2*jp+1][1][0] = t[2]; b[2*jp+1][1][1] = t[3];
        }
    };

    issue(0); cp_commit();
    if (nIt > 1) issue(1);
    cp_commit();

    for (int it = 0; it < nIt; it++) {
        if (it + 1 < nIt) cp_wait<1>(); else cp_wait<0>();
        __syncthreads();
        if (it + 2 < nIt) issue(it + 2);
        cp_commit();

        const unsigned sA0 = sb + (unsigned)((it % 3) * STAGE);
        const unsigned sB0 = sA0 + SA;

        unsigned ra[2][MT][2][4];
        unsigned rb[2][NT][2][2];
        loadA(sA0, 0, ra[0]);
        loadB(sB0, 0, rb[0]);
#pragma unroll
        for (int s = 0; s < 4; s++) {
            const int cur = s & 1;
            if (s < 3) {
                loadA(sA0, s + 1, ra[cur ^ 1]);
                loadB(sB0, s + 1, rb[cur ^ 1]);
            }
#pragma unroll
            for (int i = 0; i < MT; i++)
#pragma unroll
                for (int j = 0; j < NT; j++) {
                    mma16816(acc[i][j], ra[cur][i][0], rb[cur][j][0]);
                    mma16816(acc[i][j], ra[cur][i][0], rb[cur][j][1]);
                    mma16816(acc[i][j], ra[cur][i][1], rb[cur][j][0]);
                }
        }
        __syncthreads();
    }
    cp_wait<0>();

#pragma unroll
    for (int i = 0; i < MT; i++) {
        const int row = m0 + wm * 64 + i * 16 + (lane >> 2);
#pragma unroll
        for (int j = 0; j < NT; j++) {
            const int col = n0 + wn * (NT * 8) + j * 8 + ((lane & 3) << 1);
            float b0 = 0.f, b1 = 0.f;
            if (bias) { b0 = bias[col]; b1 = bias[col + 1]; }
#pragma unroll
            for (int hlf = 0; hlf < 2; hlf++) {
                const int r = row + hlf * 8;
                float v0 = acc[i][j][hlf * 2 + 0] * scale + b0;
                float v1 = acc[i][j][hlf * 2 + 1] * scale + b1;
                if (DOGELU) { v0 = gelu_exact(v0); v1 = gelu_exact(v1); }
                const size_t idx = (size_t)r * ldc + col;
                if (OUT == 0) {
                    if (resid) {
                        const float2 rr = *(const float2*)(resid + idx);
                        v0 += rr.x; v1 += rr.y;
                    }
                    float2 o; o.x = v0; o.y = v1;
                    *(float2*)(C + idx) = o;
                } else {
                    unsigned h, l;
                    split_pack2(v0, v1, h, l);
                    *(unsigned*)(Chi + idx) = h;
                    *(unsigned*)(Clo + idx) = l;
                }
            }
        }
    }
}

// ---------------------------------------------------------------------------
// Host orchestration
// ---------------------------------------------------------------------------
extern "C" void kernel_launch(void* const* d_in, const int* in_sizes, int n_in,
                              void* d_out, int out_size) {
    (void)in_sizes; (void)n_in; (void)out_size;
    const int*   ids   = (const int*)  d_in[0];
    const float* ctx   = (const float*)d_in[1];
    const float* tok   = (const float*)d_in[2];
    const float* pos   = (const float*)d_in[3];
    const float* qkvw  = (const float*)d_in[4];
    const float* qkvb  = (const float*)d_in[5];
    const float* projw = (const float*)d_in[6];
    const float* projb = (const float*)d_in[7];
    const float* ln1w  = (const float*)d_in[8];
    const float* ln1b  = (const float*)d_in[9];
    const float* ln2w  = (const float*)d_in[10];
    const float* ln2b  = (const float*)d_in[11];
    const float* f1w   = (const float*)d_in[12];
    const float* f1b   = (const float*)d_in[13];
    const float* f2w   = (const float*)d_in[14];
    const float* f2b   = (const float*)d_in[15];
    const float* lnfw  = (const float*)d_in[16];
    const float* lnfb  = (const float*)d_in[17];
    float* out = (float*)d_out;

    float *x;
    __nv_bfloat16 *hhi,*hlo,*qhi,*qlo,*ahi,*alo,*mhi,*mlo,*whi,*wlo;
    cudaGetSymbolAddress((void**)&x,   g_x);
    cudaGetSymbolAddress((void**)&hhi, g_h_hi);   cudaGetSymbolAddress((void**)&hlo, g_h_lo);
    cudaGetSymbolAddress((void**)&qhi, g_qkv_hi); cudaGetSymbolAddress((void**)&qlo, g_qkv_lo);
    cudaGetSymbolAddress((void**)&ahi, g_at_hi);  cudaGetSymbolAddress((void**)&alo, g_at_lo);
    cudaGetSymbolAddress((void**)&mhi, g_mid_hi); cudaGetSymbolAddress((void**)&mlo, g_mid_lo);
    cudaGetSymbolAddress((void**)&whi, g_w_hi);   cudaGetSymbolAddress((void**)&wlo, g_w_lo);

    auto kF32  = tgemm_k<128,128,0,false>;   // fp32 out (+resid)
    auto kSPL  = tgemm_k<128,128,1,false>;   // split planes out
    auto kSPLG = tgemm_k<128,128,1,true >;   // split planes out + GELU

    const int SM_NT = 3 * (2*128*128 + 2*128*128);   // 196608
    const int SM_FA = 3 * (4*128*128);               // 196608
    cudaFuncSetAttribute(kF32,    cudaFuncAttributeMaxDynamicSharedMemorySize, SM_NT);
    cudaFuncSetAttribute(kSPL,    cudaFuncAttributeMaxDynamicSharedMemorySize, SM_NT);
    cudaFuncSetAttribute(kSPLG,   cudaFuncAttributeMaxDynamicSharedMemorySize, SM_NT);
    cudaFuncSetAttribute(fattn_k, cudaFuncAttributeMaxDynamicSharedMemorySize, SM_FA);

    // ---- split all weights into bf16 hi/lo planes ----
    split_k<<<2048, 256>>>(qkvw,  whi + QW_OFF, wlo + QW_OFF, (long)(QW_SZ / 4));
    split_k<<<2048, 256>>>(projw, whi + PW_OFF, wlo + PW_OFF, (long)(PW_SZ / 4));
    split_k<<<2048, 256>>>(f1w,   whi + F1_OFF, wlo + F1_OFF, (long)(F1_SZ / 4));
    split_k<<<2048, 256>>>(f2w,   whi + F2_OFF, wlo + F2_OFF, (long)(F2_SZ / 4));
    split_k<<<2048, 256>>>(tok,   whi + TK_OFF, wlo + TK_OFF, (long)(TK_SZ / 4));

    const float attn_scale = 0.125f;   // 1/sqrt(64)

    embed_k<<<BTOK, 256>>>(ids, tok, pos, ctx, x);

    for (int l = 0; l < LAYERS; l++) {
        layernorm_split_k<<<BTOK, 256>>>(x, hhi, hlo,
                                         ln1w + (size_t)l*DM, ln1b + (size_t)l*DM);

        // qkv = h @ qkv_w^T + qkv_b  -> split planes
        kSPL<<<dim3(24, 32, 1), 256, SM_NT>>>(
            hhi, hlo, DM,
            whi + QW_OFF + (size_t)l*3*DM*DM, wlo + QW_OFF + (size_t)l*3*DM*DM, DM,
            nullptr, qhi, qlo, 3*DM,
            DM, qkvb + (size_t)l*3*DM, nullptr, 1.0f);

        // fused causal attention -> split planes
        fattn_k<<<dim3(TT/128, BBATCH*NH), 256, SM_FA>>>(
            qhi, qlo, ahi, alo, attn_scale);

        // x += attn @ proj_w^T + proj_b  (fp32 + residual)
        kF32<<<dim3(8, 32, 1), 256, SM_NT>>>(
            ahi, alo, DM,
            whi + PW_OFF + (size_t)l*DM*DM, wlo + PW_OFF + (size_t)l*DM*DM, DM,
            x, nullptr, nullptr, DM,
            DM, projb + (size_t)l*DM, x, 1.0f);

        layernorm_split_k<<<BTOK, 256>>>(x, hhi, hlo,
                                         ln2w + (size_t)l*DM, ln2b + (size_t)l*DM);

        // mid = gelu(h @ f1_w^T + f1_b) -> split planes
        kSPLG<<<dim3(32, 32, 1), 256, SM_NT>>>(
            hhi, hlo, DM,
            whi + F1_OFF + (size_t)l*4*DM*DM, wlo + F1_OFF + (size_t)l*4*DM*DM, DM,
            nullptr, mhi, mlo, 4*DM,
            DM, f1b + (size_t)l*4*DM, nullptr, 1.0f);

        // x += mid @ f2_w^T + f2_b  (fp32 + residual)
        kF32<<<dim3(8, 32, 1), 256, SM_NT>>>(
            mhi, mlo, 4*DM,
            whi + F2_OFF + (size_t)l*DM*4*DM, wlo + F2_OFF + (size_t)l*DM*4*DM, 4*DM,
            x, nullptr, nullptr, DM,
            4*DM, f2b + (size_t)l*DM, x, 1.0f);
    }

    layernorm_split_k<<<BTOK, 256>>>(x, hhi, hlo, lnfw, lnfb);

    // logits = h @ tok_emb^T (fp32)
    kF32<<<dim3(250, 32, 1), 256, SM_NT>>>(
        hhi, hlo, DM,
        whi + TK_OFF, wlo + TK_OFF, DM,
        out, nullptr, nullptr, VO,
        DM, nullptr, nullptr, 1.0f);
}